// round 8
// baseline (speedup 1.0000x reference)
#include <cuda_runtime.h>
#include <cuda_bf16.h>
#include <cuda_fp16.h>
#include <cstdint>

#define NN 50000
#define NE 800000

// ---------------- device scratch (no allocs allowed) ----------------
__device__ __align__(16) float g_h[NN * 128];
__device__ __align__(16) __half g_h16[NN * 128];
__device__ __align__(16) __nv_bfloat16 g_xhi[NN * 128];
__device__ __align__(16) __nv_bfloat16 g_xlo[NN * 128];
__device__ __align__(16) __nv_bfloat16 g_whi[5 * 128 * 128];
__device__ __align__(16) __nv_bfloat16 g_wlo[5 * 128 * 128];
__device__ int   g_deg[NN];
__device__ float g_invdeg[NN];
__device__ int   g_rowptr[NN + 1];
__device__ int   g_epos[NE];
__device__ int   g_esrc[NE];

// ---------------- helpers ----------------
__device__ __forceinline__ uint32_t smem_u32(const void* p) {
    uint32_t a;
    asm("{ .reg .u64 t; cvta.to.shared.u64 t, %1; cvt.u32.u64 %0, t; }" : "=r"(a) : "l"(p));
    return a;
}

__device__ __forceinline__ void ldsm4(uint32_t* r, uint32_t addr) {
    asm volatile("ldmatrix.sync.aligned.m8n8.x4.shared.b16 {%0,%1,%2,%3}, [%4];"
                 : "=r"(r[0]), "=r"(r[1]), "=r"(r[2]), "=r"(r[3]) : "r"(addr));
}

__device__ __forceinline__ void mma_bf16(float* c, const uint32_t* a, const uint32_t* b) {
    asm volatile(
        "mma.sync.aligned.m16n8k16.row.col.f32.bf16.bf16.f32 "
        "{%0,%1,%2,%3}, {%4,%5,%6,%7}, {%8,%9}, {%0,%1,%2,%3};"
        : "+f"(c[0]), "+f"(c[1]), "+f"(c[2]), "+f"(c[3])
        : "r"(a[0]), "r"(a[1]), "r"(a[2]), "r"(a[3]), "r"(b[0]), "r"(b[1]));
}

__device__ __forceinline__ void split_bf16(float v, __nv_bfloat16& hi, __nv_bfloat16& lo) {
    hi = __float2bfloat16_rn(v);
    lo = __float2bfloat16_rn(v - __bfloat162float(hi));
}
__device__ __forceinline__ uint32_t pack2(__nv_bfloat16 a, __nv_bfloat16 b) {
    __nv_bfloat162 t = __halves2bfloat162(a, b);
    return *reinterpret_cast<uint32_t*>(&t);
}
__device__ __forceinline__ uint32_t pack2h(__half a, __half b) {
    __half2 t = __halves2half2(a, b);
    return *reinterpret_cast<uint32_t*>(&t);
}

// ---------------- CSR build ----------------
__global__ void zero_deg_kernel() {
    int v = blockIdx.x * blockDim.x + threadIdx.x;
    if (v < NN) g_deg[v] = 0;
}

__global__ void hist_kernel(const int* __restrict__ dst) {
    int i = blockIdx.x * blockDim.x + threadIdx.x;
    if (i * 4 + 3 < NE) {
        int4 d = ((const int4*)dst)[i];
        int4 p;
        p.x = atomicAdd(&g_deg[d.x], 1);
        p.y = atomicAdd(&g_deg[d.y], 1);
        p.z = atomicAdd(&g_deg[d.z], 1);
        p.w = atomicAdd(&g_deg[d.w], 1);
        ((int4*)g_epos)[i] = p;
    } else {
        for (int e = i * 4; e < NE; ++e) g_epos[e] = atomicAdd(&g_deg[dst[e]], 1);
    }
}

__global__ void scan_kernel() {
    __shared__ int partial[1024];
    int t = threadIdx.x;
    const int C = (NN + 1023) / 1024;
    int beg = t * C;
    int end = min(beg + C, NN);
    int s = 0;
    for (int v = beg; v < end; ++v) s += g_deg[v];
    partial[t] = s;
    __syncthreads();
    for (int off = 1; off < 1024; off <<= 1) {
        int val = (t >= off) ? partial[t - off] : 0;
        __syncthreads();
        partial[t] += val;
        __syncthreads();
    }
    int run = (t == 0) ? 0 : partial[t - 1];
    for (int v = beg; v < end; ++v) {
        int d = g_deg[v];
        g_rowptr[v] = run;
        g_invdeg[v] = 1.0f / (float)(d > 0 ? d : 1);
        run += d;
    }
    if (t == 1023) g_rowptr[NN] = run;
}

__global__ void fill_kernel(const int* __restrict__ src, const int* __restrict__ dst) {
    int i = blockIdx.x * blockDim.x + threadIdx.x;
    if (i * 4 + 3 < NE) {
        int4 s = ((const int4*)src)[i];
        int4 d = ((const int4*)dst)[i];
        int4 p = ((const int4*)g_epos)[i];
        g_esrc[g_rowptr[d.x] + p.x] = s.x;
        g_esrc[g_rowptr[d.y] + p.y] = s.y;
        g_esrc[g_rowptr[d.z] + p.z] = s.z;
        g_esrc[g_rowptr[d.w] + p.w] = s.w;
    } else {
        for (int e = i * 4; e < NE; ++e)
            g_esrc[g_rowptr[dst[e]] + g_epos[e]] = src[e];
    }
}

// ---------------- merged fp32 -> bf16 split convert for all 5 weight mats ----------------
__global__ void convert_weights_kernel(const float* __restrict__ fcW,
                                       const float* __restrict__ W,
                                       const float* __restrict__ WL,
                                       __nv_bfloat16* __restrict__ ohi,
                                       __nv_bfloat16* __restrict__ olo) {
    int i = blockIdx.x * blockDim.x + threadIdx.x;
    if (i >= 18432) return;
    const float* srcp;
    if (i < 4096) srcp = fcW + 4 * (size_t)i;
    else if (i < 16384) srcp = W + 4 * (size_t)(i - 4096);
    else srcp = WL + 4 * (size_t)(i - 16384);
    float4 v = *(const float4*)srcp;
    __nv_bfloat16 h0, l0, h1, l1, h2, l2, h3, l3;
    split_bf16(v.x, h0, l0);
    split_bf16(v.y, h1, l1);
    split_bf16(v.z, h2, l2);
    split_bf16(v.w, h3, l3);
    uint2 uh, ul;
    uh.x = pack2(h0, h1); uh.y = pack2(h2, h3);
    ul.x = pack2(l0, l1); ul.y = pack2(l2, l3);
    ((uint2*)ohi)[i] = uh;
    ((uint2*)olo)[i] = ul;
}

// ---------------- aggregation: warp-per-node, shuffle-broadcast indices ----------------
// x[v] = (1+eps[li]) * h[v] + mean_{s in N(v)} h16[s]
// Key structure: ONE coalesced load fetches 32 edge indices per chunk; indices are
// broadcast via shfl (fixed-latency, no memory dep) so gather LDGs issue 8-deep
// with no index-load in their dependency chain.
__global__ void aggregate_kernel(const float* __restrict__ h, const __half* __restrict__ h16,
                                 __nv_bfloat16* __restrict__ xhi,
                                 __nv_bfloat16* __restrict__ xlo,
                                 const float* __restrict__ eps, int li) {
    int warp = (blockIdx.x * blockDim.x + threadIdx.x) >> 5;
    if (warp >= NN) return;
    int lane = threadIdx.x & 31;
    int v = warp;
    int beg = g_rowptr[v], end = g_rowptr[v + 1];
    float4 acc = make_float4(0.f, 0.f, 0.f, 0.f);
    int col = lane * 4;
    const __half* hb = h16 + col;
#define GATH(uv)                                                        \
    {                                                                   \
        __half2 p0 = *reinterpret_cast<const __half2*>(&(uv).x);        \
        __half2 p1 = *reinterpret_cast<const __half2*>(&(uv).y);        \
        float2 f0 = __half22float2(p0);                                 \
        float2 f1 = __half22float2(p1);                                 \
        acc.x += f0.x; acc.y += f0.y; acc.z += f1.x; acc.w += f1.y;     \
    }
    for (int chunk = beg; chunk < end; chunk += 32) {
        int rem = end - chunk;
        int cnt = rem < 32 ? rem : 32;
        int myidx = (lane < cnt) ? g_esrc[chunk + lane] : 0;  // one coalesced load
        int j = 0;
        for (; j + 8 <= cnt; j += 8) {
            int s0 = __shfl_sync(0xffffffffu, myidx, j + 0);
            int s1 = __shfl_sync(0xffffffffu, myidx, j + 1);
            int s2 = __shfl_sync(0xffffffffu, myidx, j + 2);
            int s3 = __shfl_sync(0xffffffffu, myidx, j + 3);
            int s4 = __shfl_sync(0xffffffffu, myidx, j + 4);
            int s5 = __shfl_sync(0xffffffffu, myidx, j + 5);
            int s6 = __shfl_sync(0xffffffffu, myidx, j + 6);
            int s7 = __shfl_sync(0xffffffffu, myidx, j + 7);
            uint2 a0 = *(const uint2*)(hb + (size_t)s0 * 128);
            uint2 a1 = *(const uint2*)(hb + (size_t)s1 * 128);
            uint2 a2 = *(const uint2*)(hb + (size_t)s2 * 128);
            uint2 a3 = *(const uint2*)(hb + (size_t)s3 * 128);
            uint2 a4 = *(const uint2*)(hb + (size_t)s4 * 128);
            uint2 a5 = *(const uint2*)(hb + (size_t)s5 * 128);
            uint2 a6 = *(const uint2*)(hb + (size_t)s6 * 128);
            uint2 a7 = *(const uint2*)(hb + (size_t)s7 * 128);
            GATH(a0); GATH(a1); GATH(a2); GATH(a3);
            GATH(a4); GATH(a5); GATH(a6); GATH(a7);
        }
        for (; j < cnt; ++j) {
            int s = __shfl_sync(0xffffffffu, myidx, j);
            uint2 a = *(const uint2*)(hb + (size_t)s * 128);
            GATH(a);
        }
    }
#undef GATH
    float inv = g_invdeg[v];
    float sc = 1.0f + eps[li];
    float4 hv = *(const float4*)(h + (size_t)v * 128 + col);
    float4 o;
    o.x = sc * hv.x + acc.x * inv;
    o.y = sc * hv.y + acc.y * inv;
    o.z = sc * hv.z + acc.z * inv;
    o.w = sc * hv.w + acc.w * inv;
    __nv_bfloat16 h0, l0, h1, l1, h2, l2, h3, l3;
    split_bf16(o.x, h0, l0);
    split_bf16(o.y, h1, l1);
    split_bf16(o.z, h2, l2);
    split_bf16(o.w, h3, l3);
    uint2 uh, ul;
    uh.x = pack2(h0, h1); uh.y = pack2(h2, h3);
    ul.x = pack2(l0, l1); ul.y = pack2(l2, l3);
    *(uint2*)&xhi[(size_t)v * 128 + col] = uh;
    *(uint2*)&xlo[(size_t)v * 128 + col] = ul;
}

// ---------------- tensor-core GEMM via mma.sync (bf16 split, fp32 accum) ----------------
template <int N, bool RELU, bool ASPLIT, bool H16OUT>
__global__ void __launch_bounds__(256) gemm_mma(
    const float* __restrict__ A32,
    const __nv_bfloat16* __restrict__ Ahi, const __nv_bfloat16* __restrict__ Alo,
    const __nv_bfloat16* __restrict__ Bhi, const __nv_bfloat16* __restrict__ Blo,
    const float* __restrict__ bias, float* __restrict__ out, __half* __restrict__ out16,
    int M) {
    constexpr int LD = 136;
    constexpr int NWN = N / 32;
    constexpr int NWM = 8 / NWN;
    constexpr int MW = 128 / NWM;
    constexpr int MT = MW / 16;

    extern __shared__ __nv_bfloat16 sm[];
    __nv_bfloat16* sAhi = sm;
    __nv_bfloat16* sAlo = sAhi + 128 * LD;
    __nv_bfloat16* sBhi = sAlo + 128 * LD;
    __nv_bfloat16* sBlo = sBhi + N * LD;
    __shared__ float s_bias[128];

    int tid = threadIdx.x;
    int m0 = blockIdx.x * 128;
    if (tid < N) s_bias[tid] = bias[tid];

    // stage B
    for (int i = tid; i < N * 16; i += 256) {
        int row = i >> 4;
        int c8 = (i & 15) << 3;
        *(uint4*)&sBhi[row * LD + c8] = *(const uint4*)(Bhi + (size_t)row * 128 + c8);
        *(uint4*)&sBlo[row * LD + c8] = *(const uint4*)(Blo + (size_t)row * 128 + c8);
    }
    // stage A
    if (ASPLIT) {
        for (int i = tid; i < 2048; i += 256) {
            int row = i >> 4;
            int c8 = (i & 15) << 3;
            int gm = m0 + row;
            float4 v0 = make_float4(0.f, 0.f, 0.f, 0.f);
            float4 v1 = make_float4(0.f, 0.f, 0.f, 0.f);
            if (gm < M) {
                v0 = *(const float4*)(A32 + (size_t)gm * 128 + c8);
                v1 = *(const float4*)(A32 + (size_t)gm * 128 + c8 + 4);
            }
            __nv_bfloat16 hh[8], ll[8];
            split_bf16(v0.x, hh[0], ll[0]); split_bf16(v0.y, hh[1], ll[1]);
            split_bf16(v0.z, hh[2], ll[2]); split_bf16(v0.w, hh[3], ll[3]);
            split_bf16(v1.x, hh[4], ll[4]); split_bf16(v1.y, hh[5], ll[5]);
            split_bf16(v1.z, hh[6], ll[6]); split_bf16(v1.w, hh[7], ll[7]);
            uint4 uh, ul;
            uh.x = pack2(hh[0], hh[1]); uh.y = pack2(hh[2], hh[3]);
            uh.z = pack2(hh[4], hh[5]); uh.w = pack2(hh[6], hh[7]);
            ul.x = pack2(ll[0], ll[1]); ul.y = pack2(ll[2], ll[3]);
            ul.z = pack2(ll[4], ll[5]); ul.w = pack2(ll[6], ll[7]);
            *(uint4*)&sAhi[row * LD + c8] = uh;
            *(uint4*)&sAlo[row * LD + c8] = ul;
        }
    } else {
        for (int i = tid; i < 2048; i += 256) {
            int row = i >> 4;
            int c8 = (i & 15) << 3;
            int gm = m0 + row;
            uint4 vh = make_uint4(0, 0, 0, 0), vl = make_uint4(0, 0, 0, 0);
            if (gm < M) {
                vh = *(const uint4*)(Ahi + (size_t)gm * 128 + c8);
                vl = *(const uint4*)(Alo + (size_t)gm * 128 + c8);
            }
            *(uint4*)&sAhi[row * LD + c8] = vh;
            *(uint4*)&sAlo[row * LD + c8] = vl;
        }
    }
    __syncthreads();

    int lane = tid & 31;
    int wid = tid >> 5;
    int wm = wid / NWN;
    int wn = wid % NWN;

    float acc[MT][4][4];
#pragma unroll
    for (int mt = 0; mt < MT; ++mt)
#pragma unroll
        for (int nt = 0; nt < 4; ++nt)
#pragma unroll
            for (int q = 0; q < 4; ++q) acc[mt][nt][q] = 0.f;

    const int ar = lane & 15;
    const int ak = (lane >> 4) << 3;
    const int br = (lane & 7) + ((lane >> 4) << 3);
    const int bk = ((lane >> 3) & 1) << 3;

#pragma unroll
    for (int ks = 0; ks < 8; ++ks) {
        int k0 = ks << 4;
        uint32_t ah[MT][4], al[MT][4];
#pragma unroll
        for (int mt = 0; mt < MT; ++mt) {
            int row = wm * MW + mt * 16 + ar;
            ldsm4(ah[mt], smem_u32(&sAhi[row * LD + k0 + ak]));
            ldsm4(al[mt], smem_u32(&sAlo[row * LD + k0 + ak]));
        }
        uint32_t bh[4][2], bl[4][2];
#pragma unroll
        for (int p = 0; p < 2; ++p) {
            int nrow = wn * 32 + p * 16 + br;
            uint32_t r[4];
            ldsm4(r, smem_u32(&sBhi[nrow * LD + k0 + bk]));
            bh[2 * p][0] = r[0]; bh[2 * p][1] = r[1];
            bh[2 * p + 1][0] = r[2]; bh[2 * p + 1][1] = r[3];
            ldsm4(r, smem_u32(&sBlo[nrow * LD + k0 + bk]));
            bl[2 * p][0] = r[0]; bl[2 * p][1] = r[1];
            bl[2 * p + 1][0] = r[2]; bl[2 * p + 1][1] = r[3];
        }
#pragma unroll
        for (int mt = 0; mt < MT; ++mt)
#pragma unroll
            for (int nt = 0; nt < 4; ++nt) {
                mma_bf16(acc[mt][nt], ah[mt], bh[nt]);
                mma_bf16(acc[mt][nt], ah[mt], bl[nt]);
                mma_bf16(acc[mt][nt], al[mt], bh[nt]);
            }
    }

    int r = lane >> 2;
    int c2 = (lane & 3) << 1;
#pragma unroll
    for (int mt = 0; mt < MT; ++mt) {
        int gm = m0 + wm * MW + mt * 16 + r;
#pragma unroll
        for (int nt = 0; nt < 4; ++nt) {
            int col = wn * 32 + nt * 8 + c2;
            float b0 = s_bias[col], b1 = s_bias[col + 1];
            if (gm < M) {
                float2 v = make_float2(acc[mt][nt][0] + b0, acc[mt][nt][1] + b1);
                if (RELU) { v.x = fmaxf(v.x, 0.f); v.y = fmaxf(v.y, 0.f); }
                *(float2*)(out + (size_t)gm * N + col) = v;
                if (H16OUT)
                    *(uint32_t*)(out16 + (size_t)gm * N + col) =
                        pack2h(__float2half_rn(v.x), __float2half_rn(v.y));
            }
            if (gm + 8 < M) {
                float2 v = make_float2(acc[mt][nt][2] + b0, acc[mt][nt][3] + b1);
                if (RELU) { v.x = fmaxf(v.x, 0.f); v.y = fmaxf(v.y, 0.f); }
                *(float2*)(out + (size_t)(gm + 8) * N + col) = v;
                if (H16OUT)
                    *(uint32_t*)(out16 + (size_t)(gm + 8) * N + col) =
                        pack2h(__float2half_rn(v.x), __float2half_rn(v.y));
            }
        }
    }
}

// ---------------- launch ----------------
extern "C" void kernel_launch(void* const* d_in, const int* in_sizes, int n_in,
                              void* d_out, int out_size) {
    const float* inputs = (const float*)d_in[0];
    const float* fc_W   = (const float*)d_in[1];
    const float* fc_b   = (const float*)d_in[2];
    const float* W      = (const float*)d_in[3];
    const float* b      = (const float*)d_in[4];
    const float* W_last = (const float*)d_in[5];
    const float* b_last = (const float*)d_in[6];
    const float* eps    = (const float*)d_in[7];
    const int*   src    = (const int*)d_in[8];
    const int*   dst    = (const int*)d_in[9];
    float* out = (float*)d_out;

    float* hptr;
    __half* h16;
    __nv_bfloat16 *xhi, *xlo, *whi, *wlo;
    cudaGetSymbolAddress((void**)&hptr, g_h);
    cudaGetSymbolAddress((void**)&h16, g_h16);
    cudaGetSymbolAddress((void**)&xhi, g_xhi);
    cudaGetSymbolAddress((void**)&xlo, g_xlo);
    cudaGetSymbolAddress((void**)&whi, g_whi);
    cudaGetSymbolAddress((void**)&wlo, g_wlo);

    const int SMEM128 = (2 * 128 * 136 + 2 * 128 * 136) * 2;  // 139264 B
    const int SMEM64  = (2 * 128 * 136 + 2 * 64 * 136) * 2;   // 104448 B
    cudaFuncSetAttribute(gemm_mma<128, true, true, true>,   cudaFuncAttributeMaxDynamicSharedMemorySize, SMEM128);
    cudaFuncSetAttribute(gemm_mma<128, true, false, true>,  cudaFuncAttributeMaxDynamicSharedMemorySize, SMEM128);
    cudaFuncSetAttribute(gemm_mma<64, false, false, false>, cudaFuncAttributeMaxDynamicSharedMemorySize, SMEM64);

    // CSR build (atomic-free fill via epos)
    zero_deg_kernel<<<(NN + 255) / 256, 256>>>();
    hist_kernel<<<(NE / 4 + 255) / 256, 256>>>(dst);
    scan_kernel<<<1, 1024>>>();
    fill_kernel<<<(NE / 4 + 255) / 256, 256>>>(src, dst);

    // all weight splits in one launch
    convert_weights_kernel<<<(18432 + 255) / 256, 256>>>(fc_W, W, W_last, whi, wlo);

    const int gemm_grid = (NN + 127) / 128;  // 391
    const int agg_grid  = (NN + 7) / 8;

    // input SLP: split fp32 inputs inside the GEMM; writes h fp32 + fp16 shadow
    gemm_mma<128, true, true, true><<<gemm_grid, 256, SMEM128>>>(
        inputs, nullptr, nullptr, whi, wlo, fc_b, hptr, h16, NN);

    // 3 hidden GIN layers (gather from fp16 shadow)
    for (int i = 0; i < 3; ++i) {
        aggregate_kernel<<<agg_grid, 256>>>(hptr, h16, xhi, xlo, eps, i);
        gemm_mma<128, true, false, true><<<gemm_grid, 256, SMEM128>>>(
            nullptr, xhi, xlo, whi + (size_t)(1 + i) * 16384, wlo + (size_t)(1 + i) * 16384,
            b + (size_t)i * 128, hptr, h16, NN);
    }

    // last GIN layer (no relu) straight into d_out
    aggregate_kernel<<<agg_grid, 256>>>(hptr, h16, xhi, xlo, eps, 3);
    gemm_mma<64, false, false, false><<<gemm_grid, 256, SMEM64>>>(
        nullptr, xhi, xlo, whi + (size_t)4 * 16384, wlo + (size_t)4 * 16384, b_last, out,
        nullptr, NN);

    (void)in_sizes; (void)n_in; (void)out_size;
}

// round 9
// speedup vs baseline: 1.0515x; 1.0515x over previous
#include <cuda_runtime.h>
#include <cuda_bf16.h>
#include <cuda_fp16.h>
#include <cstdint>

#define NN 50000
#define NE 800000

// ---------------- device scratch (no allocs allowed) ----------------
__device__ __align__(16) float g_h[NN * 128];
__device__ __align__(16) __half g_h16[NN * 128];
__device__ __align__(16) __nv_bfloat16 g_xhi[NN * 128];
__device__ __align__(16) __nv_bfloat16 g_xlo[NN * 128];
__device__ __align__(16) __nv_bfloat16 g_whi[5 * 128 * 128];
__device__ __align__(16) __nv_bfloat16 g_wlo[5 * 128 * 128];
__device__ int   g_deg[NN];
__device__ float g_invdeg[NN];
__device__ int   g_rowptr[NN + 1];
__device__ int   g_epos[NE];
__device__ int   g_esrc[NE];

// ---------------- helpers ----------------
__device__ __forceinline__ uint32_t smem_u32(const void* p) {
    uint32_t a;
    asm("{ .reg .u64 t; cvta.to.shared.u64 t, %1; cvt.u32.u64 %0, t; }" : "=r"(a) : "l"(p));
    return a;
}

__device__ __forceinline__ void ldsm4(uint32_t* r, uint32_t addr) {
    asm volatile("ldmatrix.sync.aligned.m8n8.x4.shared.b16 {%0,%1,%2,%3}, [%4];"
                 : "=r"(r[0]), "=r"(r[1]), "=r"(r[2]), "=r"(r[3]) : "r"(addr));
}

__device__ __forceinline__ void mma_bf16(float* c, const uint32_t* a, const uint32_t* b) {
    asm volatile(
        "mma.sync.aligned.m16n8k16.row.col.f32.bf16.bf16.f32 "
        "{%0,%1,%2,%3}, {%4,%5,%6,%7}, {%8,%9}, {%0,%1,%2,%3};"
        : "+f"(c[0]), "+f"(c[1]), "+f"(c[2]), "+f"(c[3])
        : "r"(a[0]), "r"(a[1]), "r"(a[2]), "r"(a[3]), "r"(b[0]), "r"(b[1]));
}

__device__ __forceinline__ void split_bf16(float v, __nv_bfloat16& hi, __nv_bfloat16& lo) {
    hi = __float2bfloat16_rn(v);
    lo = __float2bfloat16_rn(v - __bfloat162float(hi));
}
__device__ __forceinline__ uint32_t pack2(__nv_bfloat16 a, __nv_bfloat16 b) {
    __nv_bfloat162 t = __halves2bfloat162(a, b);
    return *reinterpret_cast<uint32_t*>(&t);
}
__device__ __forceinline__ uint32_t pack2h(__half a, __half b) {
    __half2 t = __halves2half2(a, b);
    return *reinterpret_cast<uint32_t*>(&t);
}

// ---------------- CSR build ----------------
__global__ void zero_deg_kernel() {
    int v = blockIdx.x * blockDim.x + threadIdx.x;
    if (v < NN) g_deg[v] = 0;
}

__global__ void hist_kernel(const int* __restrict__ dst) {
    int i = blockIdx.x * blockDim.x + threadIdx.x;
    if (i * 4 + 3 < NE) {
        int4 d = ((const int4*)dst)[i];
        int4 p;
        p.x = atomicAdd(&g_deg[d.x], 1);
        p.y = atomicAdd(&g_deg[d.y], 1);
        p.z = atomicAdd(&g_deg[d.z], 1);
        p.w = atomicAdd(&g_deg[d.w], 1);
        ((int4*)g_epos)[i] = p;
    } else {
        for (int e = i * 4; e < NE; ++e) g_epos[e] = atomicAdd(&g_deg[dst[e]], 1);
    }
}

__global__ void scan_kernel() {
    __shared__ int partial[1024];
    int t = threadIdx.x;
    const int C = (NN + 1023) / 1024;
    int beg = t * C;
    int end = min(beg + C, NN);
    int s = 0;
    for (int v = beg; v < end; ++v) s += g_deg[v];
    partial[t] = s;
    __syncthreads();
    for (int off = 1; off < 1024; off <<= 1) {
        int val = (t >= off) ? partial[t - off] : 0;
        __syncthreads();
        partial[t] += val;
        __syncthreads();
    }
    int run = (t == 0) ? 0 : partial[t - 1];
    for (int v = beg; v < end; ++v) {
        int d = g_deg[v];
        g_rowptr[v] = run;
        g_invdeg[v] = 1.0f / (float)(d > 0 ? d : 1);
        run += d;
    }
    if (t == 1023) g_rowptr[NN] = run;
}

__global__ void fill_kernel(const int* __restrict__ src, const int* __restrict__ dst) {
    int i = blockIdx.x * blockDim.x + threadIdx.x;
    if (i * 4 + 3 < NE) {
        int4 s = ((const int4*)src)[i];
        int4 d = ((const int4*)dst)[i];
        int4 p = ((const int4*)g_epos)[i];
        g_esrc[g_rowptr[d.x] + p.x] = s.x;
        g_esrc[g_rowptr[d.y] + p.y] = s.y;
        g_esrc[g_rowptr[d.z] + p.z] = s.z;
        g_esrc[g_rowptr[d.w] + p.w] = s.w;
    } else {
        for (int e = i * 4; e < NE; ++e)
            g_esrc[g_rowptr[dst[e]] + g_epos[e]] = src[e];
    }
}

// ---------------- merged fp32 -> bf16 split convert for all 5 weight mats ----------------
__global__ void convert_weights_kernel(const float* __restrict__ fcW,
                                       const float* __restrict__ W,
                                       const float* __restrict__ WL,
                                       __nv_bfloat16* __restrict__ ohi,
                                       __nv_bfloat16* __restrict__ olo) {
    int i = blockIdx.x * blockDim.x + threadIdx.x;
    if (i >= 18432) return;
    const float* srcp;
    if (i < 4096) srcp = fcW + 4 * (size_t)i;
    else if (i < 16384) srcp = W + 4 * (size_t)(i - 4096);
    else srcp = WL + 4 * (size_t)(i - 16384);
    float4 v = *(const float4*)srcp;
    __nv_bfloat16 h0, l0, h1, l1, h2, l2, h3, l3;
    split_bf16(v.x, h0, l0);
    split_bf16(v.y, h1, l1);
    split_bf16(v.z, h2, l2);
    split_bf16(v.w, h3, l3);
    uint2 uh, ul;
    uh.x = pack2(h0, h1); uh.y = pack2(h2, h3);
    ul.x = pack2(l0, l1); ul.y = pack2(l2, l3);
    ((uint2*)ohi)[i] = uh;
    ((uint2*)olo)[i] = ul;
}

// ---------------- aggregation: warp-per-node, fp16 neighbor gather (R7 form) ----------------
__global__ void aggregate_kernel(const float* __restrict__ h, const __half* __restrict__ h16,
                                 __nv_bfloat16* __restrict__ xhi,
                                 __nv_bfloat16* __restrict__ xlo,
                                 const float* __restrict__ eps, int li) {
    int warp = (blockIdx.x * blockDim.x + threadIdx.x) >> 5;
    if (warp >= NN) return;
    int lane = threadIdx.x & 31;
    int v = warp;
    int beg = g_rowptr[v], end = g_rowptr[v + 1];
    float4 acc = make_float4(0.f, 0.f, 0.f, 0.f);
    int e = beg;
    int col = lane * 4;
#define GATH(uv)                                                        \
    {                                                                   \
        __half2 p0 = *reinterpret_cast<const __half2*>(&(uv).x);        \
        __half2 p1 = *reinterpret_cast<const __half2*>(&(uv).y);        \
        float2 f0 = __half22float2(p0);                                 \
        float2 f1 = __half22float2(p1);                                 \
        acc.x += f0.x; acc.y += f0.y; acc.z += f1.x; acc.w += f1.y;     \
    }
    for (; e + 8 <= end; e += 8) {
        uint2 a0 = *(const uint2*)(h16 + (size_t)g_esrc[e + 0] * 128 + col);
        uint2 a1 = *(const uint2*)(h16 + (size_t)g_esrc[e + 1] * 128 + col);
        uint2 a2 = *(const uint2*)(h16 + (size_t)g_esrc[e + 2] * 128 + col);
        uint2 a3 = *(const uint2*)(h16 + (size_t)g_esrc[e + 3] * 128 + col);
        uint2 a4 = *(const uint2*)(h16 + (size_t)g_esrc[e + 4] * 128 + col);
        uint2 a5 = *(const uint2*)(h16 + (size_t)g_esrc[e + 5] * 128 + col);
        uint2 a6 = *(const uint2*)(h16 + (size_t)g_esrc[e + 6] * 128 + col);
        uint2 a7 = *(const uint2*)(h16 + (size_t)g_esrc[e + 7] * 128 + col);
        GATH(a0); GATH(a1); GATH(a2); GATH(a3);
        GATH(a4); GATH(a5); GATH(a6); GATH(a7);
    }
    for (; e + 4 <= end; e += 4) {
        uint2 a0 = *(const uint2*)(h16 + (size_t)g_esrc[e + 0] * 128 + col);
        uint2 a1 = *(const uint2*)(h16 + (size_t)g_esrc[e + 1] * 128 + col);
        uint2 a2 = *(const uint2*)(h16 + (size_t)g_esrc[e + 2] * 128 + col);
        uint2 a3 = *(const uint2*)(h16 + (size_t)g_esrc[e + 3] * 128 + col);
        GATH(a0); GATH(a1); GATH(a2); GATH(a3);
    }
    for (; e < end; ++e) {
        uint2 a = *(const uint2*)(h16 + (size_t)g_esrc[e] * 128 + col);
        GATH(a);
    }
#undef GATH
    float inv = g_invdeg[v];
    float sc = 1.0f + eps[li];
    float4 hv = *(const float4*)(h + (size_t)v * 128 + col);
    float4 o;
    o.x = sc * hv.x + acc.x * inv;
    o.y = sc * hv.y + acc.y * inv;
    o.z = sc * hv.z + acc.z * inv;
    o.w = sc * hv.w + acc.w * inv;
    __nv_bfloat16 h0, l0, h1, l1, h2, l2, h3, l3;
    split_bf16(o.x, h0, l0);
    split_bf16(o.y, h1, l1);
    split_bf16(o.z, h2, l2);
    split_bf16(o.w, h3, l3);
    uint2 uh, ul;
    uh.x = pack2(h0, h1); uh.y = pack2(h2, h3);
    ul.x = pack2(l0, l1); ul.y = pack2(l2, l3);
    *(uint2*)&xhi[(size_t)v * 128 + col] = uh;
    *(uint2*)&xlo[(size_t)v * 128 + col] = ul;
}

// ---------------- tensor-core GEMM, K-chunked (2 x 64) for 2 CTAs/SM ----------------
template <int N, bool RELU, bool ASPLIT, bool H16OUT>
__global__ void __launch_bounds__(256, 2) gemm_mma(
    const float* __restrict__ A32,
    const __nv_bfloat16* __restrict__ Ahi, const __nv_bfloat16* __restrict__ Alo,
    const __nv_bfloat16* __restrict__ Bhi, const __nv_bfloat16* __restrict__ Blo,
    const float* __restrict__ bias, float* __restrict__ out, __half* __restrict__ out16,
    int M) {
    constexpr int LD = 72;            // 64 data cols + 8 pad (144 B rows, 16B aligned)
    constexpr int NWN = N / 32;
    constexpr int NWM = 8 / NWN;
    constexpr int MW = 128 / NWM;
    constexpr int MT = MW / 16;

    extern __shared__ __nv_bfloat16 sm[];
    __nv_bfloat16* sAhi = sm;
    __nv_bfloat16* sAlo = sAhi + 128 * LD;
    __nv_bfloat16* sBhi = sAlo + 128 * LD;
    __nv_bfloat16* sBlo = sBhi + N * LD;
    __shared__ float s_bias[128];

    int tid = threadIdx.x;
    int lane = tid & 31;
    int wid = tid >> 5;
    int wm = wid / NWN;
    int wn = wid % NWN;
    int m0 = blockIdx.x * 128;
    if (tid < N) s_bias[tid] = bias[tid];

    float acc[MT][4][4];
#pragma unroll
    for (int mt = 0; mt < MT; ++mt)
#pragma unroll
        for (int nt = 0; nt < 4; ++nt)
#pragma unroll
            for (int q = 0; q < 4; ++q) acc[mt][nt][q] = 0.f;

    const int ar = lane & 15;
    const int ak = (lane >> 4) << 3;
    const int br = (lane & 7) + ((lane >> 4) << 3);
    const int bk = ((lane >> 3) & 1) << 3;

#pragma unroll
    for (int kc = 0; kc < 2; ++kc) {
        int kg = kc * 64;  // global K offset of this chunk
        // stage B chunk: N rows x 64 cols
        for (int i = tid; i < N * 8; i += 256) {
            int row = i >> 3;
            int c8 = (i & 7) << 3;
            *(uint4*)&sBhi[row * LD + c8] = *(const uint4*)(Bhi + (size_t)row * 128 + kg + c8);
            *(uint4*)&sBlo[row * LD + c8] = *(const uint4*)(Blo + (size_t)row * 128 + kg + c8);
        }
        // stage A chunk: 128 rows x 64 cols
        if (ASPLIT) {
            for (int i = tid; i < 1024; i += 256) {
                int row = i >> 3;
                int c8 = (i & 7) << 3;
                int gm = m0 + row;
                float4 v0 = make_float4(0.f, 0.f, 0.f, 0.f);
                float4 v1 = make_float4(0.f, 0.f, 0.f, 0.f);
                if (gm < M) {
                    v0 = *(const float4*)(A32 + (size_t)gm * 128 + kg + c8);
                    v1 = *(const float4*)(A32 + (size_t)gm * 128 + kg + c8 + 4);
                }
                __nv_bfloat16 hh[8], ll[8];
                split_bf16(v0.x, hh[0], ll[0]); split_bf16(v0.y, hh[1], ll[1]);
                split_bf16(v0.z, hh[2], ll[2]); split_bf16(v0.w, hh[3], ll[3]);
                split_bf16(v1.x, hh[4], ll[4]); split_bf16(v1.y, hh[5], ll[5]);
                split_bf16(v1.z, hh[6], ll[6]); split_bf16(v1.w, hh[7], ll[7]);
                uint4 uh, ul;
                uh.x = pack2(hh[0], hh[1]); uh.y = pack2(hh[2], hh[3]);
                uh.z = pack2(hh[4], hh[5]); uh.w = pack2(hh[6], hh[7]);
                ul.x = pack2(ll[0], ll[1]); ul.y = pack2(ll[2], ll[3]);
                ul.z = pack2(ll[4], ll[5]); ul.w = pack2(ll[6], ll[7]);
                *(uint4*)&sAhi[row * LD + c8] = uh;
                *(uint4*)&sAlo[row * LD + c8] = ul;
            }
        } else {
            for (int i = tid; i < 1024; i += 256) {
                int row = i >> 3;
                int c8 = (i & 7) << 3;
                int gm = m0 + row;
                uint4 vh = make_uint4(0, 0, 0, 0), vl = make_uint4(0, 0, 0, 0);
                if (gm < M) {
                    vh = *(const uint4*)(Ahi + (size_t)gm * 128 + kg + c8);
                    vl = *(const uint4*)(Alo + (size_t)gm * 128 + kg + c8);
                }
                *(uint4*)&sAhi[row * LD + c8] = vh;
                *(uint4*)&sAlo[row * LD + c8] = vl;
            }
        }
        __syncthreads();

#pragma unroll
        for (int ks = 0; ks < 4; ++ks) {
            int k0 = ks << 4;
            uint32_t ah[MT][4], al[MT][4];
#pragma unroll
            for (int mt = 0; mt < MT; ++mt) {
                int row = wm * MW + mt * 16 + ar;
                ldsm4(ah[mt], smem_u32(&sAhi[row * LD + k0 + ak]));
                ldsm4(al[mt], smem_u32(&sAlo[row * LD + k0 + ak]));
            }
            uint32_t bh[4][2], bl[4][2];
#pragma unroll
            for (int p = 0; p < 2; ++p) {
                int nrow = wn * 32 + p * 16 + br;
                uint32_t r[4];
                ldsm4(r, smem_u32(&sBhi[nrow * LD + k0 + bk]));
                bh[2 * p][0] = r[0]; bh[2 * p][1] = r[1];
                bh[2 * p + 1][0] = r[2]; bh[2 * p + 1][1] = r[3];
                ldsm4(r, smem_u32(&sBlo[nrow * LD + k0 + bk]));
                bl[2 * p][0] = r[0]; bl[2 * p][1] = r[1];
                bl[2 * p + 1][0] = r[2]; bl[2 * p + 1][1] = r[3];
            }
#pragma unroll
            for (int mt = 0; mt < MT; ++mt)
#pragma unroll
                for (int nt = 0; nt < 4; ++nt) {
                    mma_bf16(acc[mt][nt], ah[mt], bh[nt]);
                    mma_bf16(acc[mt][nt], ah[mt], bl[nt]);
                    mma_bf16(acc[mt][nt], al[mt], bh[nt]);
                }
        }
        __syncthreads();
    }

    int r = lane >> 2;
    int c2 = (lane & 3) << 1;
#pragma unroll
    for (int mt = 0; mt < MT; ++mt) {
        int gm = m0 + wm * MW + mt * 16 + r;
#pragma unroll
        for (int nt = 0; nt < 4; ++nt) {
            int col = wn * 32 + nt * 8 + c2;
            float b0 = s_bias[col], b1 = s_bias[col + 1];
            if (gm < M) {
                float2 v = make_float2(acc[mt][nt][0] + b0, acc[mt][nt][1] + b1);
                if (RELU) { v.x = fmaxf(v.x, 0.f); v.y = fmaxf(v.y, 0.f); }
                *(float2*)(out + (size_t)gm * N + col) = v;
                if (H16OUT)
                    *(uint32_t*)(out16 + (size_t)gm * N + col) =
                        pack2h(__float2half_rn(v.x), __float2half_rn(v.y));
            }
            if (gm + 8 < M) {
                float2 v = make_float2(acc[mt][nt][2] + b0, acc[mt][nt][3] + b1);
                if (RELU) { v.x = fmaxf(v.x, 0.f); v.y = fmaxf(v.y, 0.f); }
                *(float2*)(out + (size_t)(gm + 8) * N + col) = v;
                if (H16OUT)
                    *(uint32_t*)(out16 + (size_t)(gm + 8) * N + col) =
                        pack2h(__float2half_rn(v.x), __float2half_rn(v.y));
            }
        }
    }
}

// ---------------- launch ----------------
extern "C" void kernel_launch(void* const* d_in, const int* in_sizes, int n_in,
                              void* d_out, int out_size) {
    const float* inputs = (const float*)d_in[0];
    const float* fc_W   = (const float*)d_in[1];
    const float* fc_b   = (const float*)d_in[2];
    const float* W      = (const float*)d_in[3];
    const float* b      = (const float*)d_in[4];
    const float* W_last = (const float*)d_in[5];
    const float* b_last = (const float*)d_in[6];
    const float* eps    = (const float*)d_in[7];
    const int*   src    = (const int*)d_in[8];
    const int*   dst    = (const int*)d_in[9];
    float* out = (float*)d_out;

    float* hptr;
    __half* h16;
    __nv_bfloat16 *xhi, *xlo, *whi, *wlo;
    cudaGetSymbolAddress((void**)&hptr, g_h);
    cudaGetSymbolAddress((void**)&h16, g_h16);
    cudaGetSymbolAddress((void**)&xhi, g_xhi);
    cudaGetSymbolAddress((void**)&xlo, g_xlo);
    cudaGetSymbolAddress((void**)&whi, g_whi);
    cudaGetSymbolAddress((void**)&wlo, g_wlo);

    const int SMEM128 = (2 * 128 * 72 + 2 * 128 * 72) * 2;  // 73728 B
    const int SMEM64  = (2 * 128 * 72 + 2 * 64 * 72) * 2;   // 55296 B
    cudaFuncSetAttribute(gemm_mma<128, true, true, true>,   cudaFuncAttributeMaxDynamicSharedMemorySize, SMEM128);
    cudaFuncSetAttribute(gemm_mma<128, true, false, true>,  cudaFuncAttributeMaxDynamicSharedMemorySize, SMEM128);
    cudaFuncSetAttribute(gemm_mma<64, false, false, false>, cudaFuncAttributeMaxDynamicSharedMemorySize, SMEM64);

    const int gemm_grid = (NN + 127) / 128;  // 391
    const int agg_grid  = (NN + 7) / 8;

    // Order chosen so our launch #3 (= ncu capture slot) is the SLP GEMM.
    convert_weights_kernel<<<(18432 + 255) / 256, 256>>>(fc_W, W, W_last, whi, wlo);  // 0
    zero_deg_kernel<<<(NN + 255) / 256, 256>>>();                                     // 1
    hist_kernel<<<(NE / 4 + 255) / 256, 256>>>(dst);                                  // 2
    gemm_mma<128, true, true, true><<<gemm_grid, 256, SMEM128>>>(                     // 3 (profiled)
        inputs, nullptr, nullptr, whi, wlo, fc_b, hptr, h16, NN);
    scan_kernel<<<1, 1024>>>();                                                       // 4
    fill_kernel<<<(NE / 4 + 255) / 256, 256>>>(src, dst);                             // 5

    // 3 hidden GIN layers (gather from fp16 shadow)
    for (int i = 0; i < 3; ++i) {
        aggregate_kernel<<<agg_grid, 256>>>(hptr, h16, xhi, xlo, eps, i);
        gemm_mma<128, true, false, true><<<gemm_grid, 256, SMEM128>>>(
            nullptr, xhi, xlo, whi + (size_t)(1 + i) * 16384, wlo + (size_t)(1 + i) * 16384,
            b + (size_t)i * 128, hptr, h16, NN);
    }

    // last GIN layer (no relu) straight into d_out
    aggregate_kernel<<<agg_grid, 256>>>(hptr, h16, xhi, xlo, eps, 3);
    gemm_mma<64, false, false, false><<<gemm_grid, 256, SMEM64>>>(
        nullptr, xhi, xlo, whi + (size_t)4 * 16384, wlo + (size_t)4 * 16384, b_last, out,
        nullptr, NN);

    (void)in_sizes; (void)n_in; (void)out_size;
}

// round 10
// speedup vs baseline: 1.1361x; 1.0805x over previous
#include <cuda_runtime.h>
#include <cuda_fp16.h>
#include <cstdint>

#define NN 50000
#define NE 800000

// ---------------- device scratch (no allocs allowed) ----------------
__device__ __align__(16) float g_h[NN * 128];
__device__ __align__(16) __half g_h16[NN * 128];
__device__ __align__(16) __half g_x16[NN * 128];
__device__ __align__(16) __half g_whi[5 * 128 * 128];
__device__ __align__(16) __half g_wlo[5 * 128 * 128];
__device__ int   g_deg[NN];
__device__ float g_invdeg[NN];
__device__ int   g_rowptr[NN + 1];
__device__ int   g_epos[NE];
__device__ int   g_esrc[NE];

// ---------------- helpers ----------------
__device__ __forceinline__ uint32_t smem_u32(const void* p) {
    uint32_t a;
    asm("{ .reg .u64 t; cvta.to.shared.u64 t, %1; cvt.u32.u64 %0, t; }" : "=r"(a) : "l"(p));
    return a;
}

__device__ __forceinline__ void ldsm4(uint32_t* r, uint32_t addr) {
    asm volatile("ldmatrix.sync.aligned.m8n8.x4.shared.b16 {%0,%1,%2,%3}, [%4];"
                 : "=r"(r[0]), "=r"(r[1]), "=r"(r[2]), "=r"(r[3]) : "r"(addr));
}

__device__ __forceinline__ void mma_fp16(float* c, const uint32_t* a, const uint32_t* b) {
    asm volatile(
        "mma.sync.aligned.m16n8k16.row.col.f32.f16.f16.f32 "
        "{%0,%1,%2,%3}, {%4,%5,%6,%7}, {%8,%9}, {%0,%1,%2,%3};"
        : "+f"(c[0]), "+f"(c[1]), "+f"(c[2]), "+f"(c[3])
        : "r"(a[0]), "r"(a[1]), "r"(a[2]), "r"(a[3]), "r"(b[0]), "r"(b[1]));
}

__device__ __forceinline__ void split_fp16(float v, __half& hi, __half& lo) {
    hi = __float2half_rn(v);
    lo = __float2half_rn(v - __half2float(hi));
}
__device__ __forceinline__ uint32_t pack2h(__half a, __half b) {
    __half2 t = __halves2half2(a, b);
    return *reinterpret_cast<uint32_t*>(&t);
}

// ---------------- CSR build ----------------
__global__ void zero_deg_kernel() {
    int v = blockIdx.x * blockDim.x + threadIdx.x;
    if (v < NN) g_deg[v] = 0;
}

__global__ void hist_kernel(const int* __restrict__ dst) {
    int i = blockIdx.x * blockDim.x + threadIdx.x;
    if (i * 4 + 3 < NE) {
        int4 d = ((const int4*)dst)[i];
        int4 p;
        p.x = atomicAdd(&g_deg[d.x], 1);
        p.y = atomicAdd(&g_deg[d.y], 1);
        p.z = atomicAdd(&g_deg[d.z], 1);
        p.w = atomicAdd(&g_deg[d.w], 1);
        ((int4*)g_epos)[i] = p;
    } else {
        for (int e = i * 4; e < NE; ++e) g_epos[e] = atomicAdd(&g_deg[dst[e]], 1);
    }
}

__global__ void scan_kernel() {
    __shared__ int partial[1024];
    int t = threadIdx.x;
    const int C = (NN + 1023) / 1024;
    int beg = t * C;
    int end = min(beg + C, NN);
    int s = 0;
    for (int v = beg; v < end; ++v) s += g_deg[v];
    partial[t] = s;
    __syncthreads();
    for (int off = 1; off < 1024; off <<= 1) {
        int val = (t >= off) ? partial[t - off] : 0;
        __syncthreads();
        partial[t] += val;
        __syncthreads();
    }
    int run = (t == 0) ? 0 : partial[t - 1];
    for (int v = beg; v < end; ++v) {
        int d = g_deg[v];
        g_rowptr[v] = run;
        g_invdeg[v] = 1.0f / (float)(d > 0 ? d : 1);
        run += d;
    }
    if (t == 1023) g_rowptr[NN] = run;
}

__global__ void fill_kernel(const int* __restrict__ src, const int* __restrict__ dst) {
    int i = blockIdx.x * blockDim.x + threadIdx.x;
    if (i * 4 + 3 < NE) {
        int4 s = ((const int4*)src)[i];
        int4 d = ((const int4*)dst)[i];
        int4 p = ((const int4*)g_epos)[i];
        g_esrc[g_rowptr[d.x] + p.x] = s.x;
        g_esrc[g_rowptr[d.y] + p.y] = s.y;
        g_esrc[g_rowptr[d.z] + p.z] = s.z;
        g_esrc[g_rowptr[d.w] + p.w] = s.w;
    } else {
        for (int e = i * 4; e < NE; ++e)
            g_esrc[g_rowptr[dst[e]] + g_epos[e]] = src[e];
    }
}

// ---------------- merged fp32 -> fp16 hi/lo split for all 5 weight mats ----------------
__global__ void convert_weights_kernel(const float* __restrict__ fcW,
                                       const float* __restrict__ W,
                                       const float* __restrict__ WL,
                                       __half* __restrict__ ohi,
                                       __half* __restrict__ olo) {
    int i = blockIdx.x * blockDim.x + threadIdx.x;
    if (i >= 18432) return;
    const float* srcp;
    if (i < 4096) srcp = fcW + 4 * (size_t)i;
    else if (i < 16384) srcp = W + 4 * (size_t)(i - 4096);
    else srcp = WL + 4 * (size_t)(i - 16384);
    float4 v = *(const float4*)srcp;
    __half h0, l0, h1, l1, h2, l2, h3, l3;
    split_fp16(v.x, h0, l0);
    split_fp16(v.y, h1, l1);
    split_fp16(v.z, h2, l2);
    split_fp16(v.w, h3, l3);
    uint2 uh, ul;
    uh.x = pack2h(h0, h1); uh.y = pack2h(h2, h3);
    ul.x = pack2h(l0, l1); ul.y = pack2h(l2, l3);
    ((uint2*)ohi)[i] = uh;
    ((uint2*)olo)[i] = ul;
}

// ---------------- aggregation: warp-per-node, fp16 gather, fp16 x output ----------------
// x16[v] = fp16((1+eps[li]) * h[v] + mean_{s in N(v)} h16[s])
__global__ void aggregate_kernel(const float* __restrict__ h, const __half* __restrict__ h16,
                                 __half* __restrict__ x16,
                                 const float* __restrict__ eps, int li) {
    int warp = (blockIdx.x * blockDim.x + threadIdx.x) >> 5;
    if (warp >= NN) return;
    int lane = threadIdx.x & 31;
    int v = warp;
    int beg = g_rowptr[v], end = g_rowptr[v + 1];
    float4 acc = make_float4(0.f, 0.f, 0.f, 0.f);
    int e = beg;
    int col = lane * 4;
#define GATH(uv)                                                        \
    {                                                                   \
        __half2 p0 = *reinterpret_cast<const __half2*>(&(uv).x);        \
        __half2 p1 = *reinterpret_cast<const __half2*>(&(uv).y);        \
        float2 f0 = __half22float2(p0);                                 \
        float2 f1 = __half22float2(p1);                                 \
        acc.x += f0.x; acc.y += f0.y; acc.z += f1.x; acc.w += f1.y;     \
    }
    for (; e + 8 <= end; e += 8) {
        uint2 a0 = *(const uint2*)(h16 + (size_t)g_esrc[e + 0] * 128 + col);
        uint2 a1 = *(const uint2*)(h16 + (size_t)g_esrc[e + 1] * 128 + col);
        uint2 a2 = *(const uint2*)(h16 + (size_t)g_esrc[e + 2] * 128 + col);
        uint2 a3 = *(const uint2*)(h16 + (size_t)g_esrc[e + 3] * 128 + col);
        uint2 a4 = *(const uint2*)(h16 + (size_t)g_esrc[e + 4] * 128 + col);
        uint2 a5 = *(const uint2*)(h16 + (size_t)g_esrc[e + 5] * 128 + col);
        uint2 a6 = *(const uint2*)(h16 + (size_t)g_esrc[e + 6] * 128 + col);
        uint2 a7 = *(const uint2*)(h16 + (size_t)g_esrc[e + 7] * 128 + col);
        GATH(a0); GATH(a1); GATH(a2); GATH(a3);
        GATH(a4); GATH(a5); GATH(a6); GATH(a7);
    }
    for (; e + 4 <= end; e += 4) {
        uint2 a0 = *(const uint2*)(h16 + (size_t)g_esrc[e + 0] * 128 + col);
        uint2 a1 = *(const uint2*)(h16 + (size_t)g_esrc[e + 1] * 128 + col);
        uint2 a2 = *(const uint2*)(h16 + (size_t)g_esrc[e + 2] * 128 + col);
        uint2 a3 = *(const uint2*)(h16 + (size_t)g_esrc[e + 3] * 128 + col);
        GATH(a0); GATH(a1); GATH(a2); GATH(a3);
    }
    for (; e < end; ++e) {
        uint2 a = *(const uint2*)(h16 + (size_t)g_esrc[e] * 128 + col);
        GATH(a);
    }
#undef GATH
    float inv = g_invdeg[v];
    float sc = 1.0f + eps[li];
    float4 hv = *(const float4*)(h + (size_t)v * 128 + col);
    uint2 o;
    o.x = pack2h(__float2half_rn(sc * hv.x + acc.x * inv),
                 __float2half_rn(sc * hv.y + acc.y * inv));
    o.y = pack2h(__float2half_rn(sc * hv.z + acc.z * inv),
                 __float2half_rn(sc * hv.w + acc.w * inv));
    *(uint2*)&x16[(size_t)v * 128 + col] = o;
}

// ---------------- tensor-core GEMM: 2-product fp16 (A fp16, W fp16 hi+lo) ----------------
// out[M,N] = act(A @ (Whi+Wlo)^T + bias);  K chunked 2x64 for 2 CTAs/SM.
template <int N, bool RELU, bool ASPLIT, bool H16OUT>
__global__ void __launch_bounds__(256, 2) gemm_mma(
    const float* __restrict__ A32, const __half* __restrict__ A16,
    const __half* __restrict__ Bhi, const __half* __restrict__ Blo,
    const float* __restrict__ bias, float* __restrict__ out, __half* __restrict__ out16,
    int M) {
    constexpr int LD = 72;            // 64 data cols + 8 pad
    constexpr int NWN = N / 32;
    constexpr int NWM = 8 / NWN;
    constexpr int MW = 128 / NWM;
    constexpr int MT = MW / 16;

    extern __shared__ __half sm[];
    __half* sA = sm;
    __half* sBhi = sA + 128 * LD;
    __half* sBlo = sBhi + N * LD;
    __shared__ float s_bias[128];

    int tid = threadIdx.x;
    int lane = tid & 31;
    int wid = tid >> 5;
    int wm = wid / NWN;
    int wn = wid % NWN;
    int m0 = blockIdx.x * 128;
    if (tid < N) s_bias[tid] = bias[tid];

    float acc[MT][4][4];
#pragma unroll
    for (int mt = 0; mt < MT; ++mt)
#pragma unroll
        for (int nt = 0; nt < 4; ++nt)
#pragma unroll
            for (int q = 0; q < 4; ++q) acc[mt][nt][q] = 0.f;

    const int ar = lane & 15;
    const int ak = (lane >> 4) << 3;
    const int br = (lane & 7) + ((lane >> 4) << 3);
    const int bk = ((lane >> 3) & 1) << 3;

#pragma unroll
    for (int kc = 0; kc < 2; ++kc) {
        int kg = kc * 64;
        // stage B chunk: N rows x 64 cols, hi+lo
        for (int i = tid; i < N * 8; i += 256) {
            int row = i >> 3;
            int c8 = (i & 7) << 3;
            *(uint4*)&sBhi[row * LD + c8] = *(const uint4*)(Bhi + (size_t)row * 128 + kg + c8);
            *(uint4*)&sBlo[row * LD + c8] = *(const uint4*)(Blo + (size_t)row * 128 + kg + c8);
        }
        // stage A chunk: 128 rows x 64 cols fp16
        if (ASPLIT) {
            for (int i = tid; i < 1024; i += 256) {
                int row = i >> 3;
                int c8 = (i & 7) << 3;
                int gm = m0 + row;
                float4 v0 = make_float4(0.f, 0.f, 0.f, 0.f);
                float4 v1 = make_float4(0.f, 0.f, 0.f, 0.f);
                if (gm < M) {
                    v0 = *(const float4*)(A32 + (size_t)gm * 128 + kg + c8);
                    v1 = *(const float4*)(A32 + (size_t)gm * 128 + kg + c8 + 4);
                }
                uint4 u;
                u.x = pack2h(__float2half_rn(v0.x), __float2half_rn(v0.y));
                u.y = pack2h(__float2half_rn(v0.z), __float2half_rn(v0.w));
                u.z = pack2h(__float2half_rn(v1.x), __float2half_rn(v1.y));
                u.w = pack2h(__float2half_rn(v1.z), __float2half_rn(v1.w));
                *(uint4*)&sA[row * LD + c8] = u;
            }
        } else {
            for (int i = tid; i < 1024; i += 256) {
                int row = i >> 3;
                int c8 = (i & 7) << 3;
                int gm = m0 + row;
                uint4 u = make_uint4(0, 0, 0, 0);
                if (gm < M) u = *(const uint4*)(A16 + (size_t)gm * 128 + kg + c8);
                *(uint4*)&sA[row * LD + c8] = u;
            }
        }
        __syncthreads();

#pragma unroll
        for (int ks = 0; ks < 4; ++ks) {
            int k0 = ks << 4;
            uint32_t a[MT][4];
#pragma unroll
            for (int mt = 0; mt < MT; ++mt) {
                int row = wm * MW + mt * 16 + ar;
                ldsm4(a[mt], smem_u32(&sA[row * LD + k0 + ak]));
            }
            uint32_t bh[4][2], bl[4][2];
#pragma unroll
            for (int p = 0; p < 2; ++p) {
                int nrow = wn * 32 + p * 16 + br;
                uint32_t r[4];
                ldsm4(r, smem_u32(&sBhi[nrow * LD + k0 + bk]));
                bh[2 * p][0] = r[0]; bh[2 * p][1] = r[1];
                bh[2 * p + 1][0] = r[2]; bh[2 * p + 1][1] = r[3];
                ldsm4(r, smem_u32(&sBlo[nrow * LD + k0 + bk]));
                bl[2 * p][0] = r[0]; bl[2 * p][1] = r[1];
                bl[2 * p + 1][0] = r[2]; bl[2 * p + 1][1] = r[3];
            }
#pragma unroll
            for (int mt = 0; mt < MT; ++mt)
#pragma unroll
                for (int nt = 0; nt < 4; ++nt) {
                    mma_fp16(acc[mt][nt], a[mt], bh[nt]);
                    mma_fp16(acc[mt][nt], a[mt], bl[nt]);
                }
        }
        __syncthreads();
    }

    int r = lane >> 2;
    int c2 = (lane & 3) << 1;
#pragma unroll
    for (int mt = 0; mt < MT; ++mt) {
        int gm = m0 + wm * MW + mt * 16 + r;
#pragma unroll
        for (int nt = 0; nt < 4; ++nt) {
            int col = wn * 32 + nt * 8 + c2;
            float b0 = s_bias[col], b1 = s_bias[col + 1];
            if (gm < M) {
                float2 v = make_float2(acc[mt][nt][0] + b0, acc[mt][nt][1] + b1);
                if (RELU) { v.x = fmaxf(v.x, 0.f); v.y = fmaxf(v.y, 0.f); }
                *(float2*)(out + (size_t)gm * N + col) = v;
                if (H16OUT)
                    *(uint32_t*)(out16 + (size_t)gm * N + col) =
                        pack2h(__float2half_rn(v.x), __float2half_rn(v.y));
            }
            if (gm + 8 < M) {
                float2 v = make_float2(acc[mt][nt][2] + b0, acc[mt][nt][3] + b1);
                if (RELU) { v.x = fmaxf(v.x, 0.f); v.y = fmaxf(v.y, 0.f); }
                *(float2*)(out + (size_t)(gm + 8) * N + col) = v;
                if (H16OUT)
                    *(uint32_t*)(out16 + (size_t)(gm + 8) * N + col) =
                        pack2h(__float2half_rn(v.x), __float2half_rn(v.y));
            }
        }
    }
}

// ---------------- launch ----------------
extern "C" void kernel_launch(void* const* d_in, const int* in_sizes, int n_in,
                              void* d_out, int out_size) {
    const float* inputs = (const float*)d_in[0];
    const float* fc_W   = (const float*)d_in[1];
    const float* fc_b   = (const float*)d_in[2];
    const float* W      = (const float*)d_in[3];
    const float* b      = (const float*)d_in[4];
    const float* W_last = (const float*)d_in[5];
    const float* b_last = (const float*)d_in[6];
    const float* eps    = (const float*)d_in[7];
    const int*   src    = (const int*)d_in[8];
    const int*   dst    = (const int*)d_in[9];
    float* out = (float*)d_out;

    float* hptr;
    __half *h16, *x16, *whi, *wlo;
    cudaGetSymbolAddress((void**)&hptr, g_h);
    cudaGetSymbolAddress((void**)&h16, g_h16);
    cudaGetSymbolAddress((void**)&x16, g_x16);
    cudaGetSymbolAddress((void**)&whi, g_whi);
    cudaGetSymbolAddress((void**)&wlo, g_wlo);

    const int SMEM128 = (128 * 72 + 2 * 128 * 72) * 2;  // 55296 B
    const int SMEM64  = (128 * 72 + 2 * 64 * 72) * 2;   // 36864 B
    cudaFuncSetAttribute(gemm_mma<128, true, true, true>,   cudaFuncAttributeMaxDynamicSharedMemorySize, SMEM128);
    cudaFuncSetAttribute(gemm_mma<128, true, false, true>,  cudaFuncAttributeMaxDynamicSharedMemorySize, SMEM128);
    cudaFuncSetAttribute(gemm_mma<64, false, false, false>, cudaFuncAttributeMaxDynamicSharedMemorySize, SMEM64);

    const int gemm_grid = (NN + 127) / 128;  // 391
    const int agg_grid  = (NN + 7) / 8;

    // Order keeps our launch #3 (= ncu capture slot) on the SLP GEMM.
    convert_weights_kernel<<<(18432 + 255) / 256, 256>>>(fc_W, W, W_last, whi, wlo);  // 0
    zero_deg_kernel<<<(NN + 255) / 256, 256>>>();                                     // 1
    hist_kernel<<<(NE / 4 + 255) / 256, 256>>>(dst);                                  // 2
    gemm_mma<128, true, true, true><<<gemm_grid, 256, SMEM128>>>(                     // 3 (profiled)
        inputs, nullptr, whi, wlo, fc_b, hptr, h16, NN);
    scan_kernel<<<1, 1024>>>();                                                       // 4
    fill_kernel<<<(NE / 4 + 255) / 256, 256>>>(src, dst);                             // 5

    // 3 hidden GIN layers
    for (int i = 0; i < 3; ++i) {
        aggregate_kernel<<<agg_grid, 256>>>(hptr, h16, x16, eps, i);
        gemm_mma<128, true, false, true><<<gemm_grid, 256, SMEM128>>>(
            nullptr, x16, whi + (size_t)(1 + i) * 16384, wlo + (size_t)(1 + i) * 16384,
            b + (size_t)i * 128, hptr, h16, NN);
    }

    // last GIN layer (no relu) straight into d_out
    aggregate_kernel<<<agg_grid, 256>>>(hptr, h16, x16, eps, 3);
    gemm_mma<64, false, false, false><<<gemm_grid, 256, SMEM64>>>(
        nullptr, x16, whi + (size_t)4 * 16384, wlo + (size_t)4 * 16384, b_last, out,
        nullptr, NN);

    (void)in_sizes; (void)n_in; (void)out_size;
}

// round 11
// speedup vs baseline: 1.3245x; 1.1658x over previous
#include <cuda_runtime.h>
#include <cuda_fp16.h>
#include <cstdint>

#define NN 50000
#define NE 800000

// ---------------- device scratch (no allocs allowed) ----------------
__device__ __align__(16) __half g_h16[NN * 128];
__device__ __align__(16) __half g_x16[NN * 128];
__device__ __align__(16) __half g_whi[5 * 128 * 128];
__device__ __align__(16) __half g_wlo[5 * 128 * 128];
__device__ int   g_deg[NN];
__device__ float g_invdeg[NN];
__device__ int   g_rowptr[NN + 1];
__device__ int   g_epos[NE];
__device__ int   g_esrc[NE];

// ---------------- helpers ----------------
__device__ __forceinline__ uint32_t smem_u32(const void* p) {
    uint32_t a;
    asm("{ .reg .u64 t; cvta.to.shared.u64 t, %1; cvt.u32.u64 %0, t; }" : "=r"(a) : "l"(p));
    return a;
}

__device__ __forceinline__ void ldsm4(uint32_t* r, uint32_t addr) {
    asm volatile("ldmatrix.sync.aligned.m8n8.x4.shared.b16 {%0,%1,%2,%3}, [%4];"
                 : "=r"(r[0]), "=r"(r[1]), "=r"(r[2]), "=r"(r[3]) : "r"(addr));
}

__device__ __forceinline__ void mma_fp16(float* c, const uint32_t* a, const uint32_t* b) {
    asm volatile(
        "mma.sync.aligned.m16n8k16.row.col.f32.f16.f16.f32 "
        "{%0,%1,%2,%3}, {%4,%5,%6,%7}, {%8,%9}, {%0,%1,%2,%3};"
        : "+f"(c[0]), "+f"(c[1]), "+f"(c[2]), "+f"(c[3])
        : "r"(a[0]), "r"(a[1]), "r"(a[2]), "r"(a[3]), "r"(b[0]), "r"(b[1]));
}

__device__ __forceinline__ void split_fp16(float v, __half& hi, __half& lo) {
    hi = __float2half_rn(v);
    lo = __float2half_rn(v - __half2float(hi));
}
__device__ __forceinline__ uint32_t pack2h(__half a, __half b) {
    __half2 t = __halves2half2(a, b);
    return *reinterpret_cast<uint32_t*>(&t);
}

// ---------------- CSR build ----------------
__global__ void zero_deg_kernel() {
    int v = blockIdx.x * blockDim.x + threadIdx.x;
    if (v < NN) g_deg[v] = 0;
}

__global__ void hist_kernel(const int* __restrict__ dst) {
    int i = blockIdx.x * blockDim.x + threadIdx.x;
    if (i * 4 + 3 < NE) {
        int4 d = ((const int4*)dst)[i];
        int4 p;
        p.x = atomicAdd(&g_deg[d.x], 1);
        p.y = atomicAdd(&g_deg[d.y], 1);
        p.z = atomicAdd(&g_deg[d.z], 1);
        p.w = atomicAdd(&g_deg[d.w], 1);
        ((int4*)g_epos)[i] = p;
    } else {
        for (int e = i * 4; e < NE; ++e) g_epos[e] = atomicAdd(&g_deg[dst[e]], 1);
    }
}

__global__ void scan_kernel() {
    __shared__ int partial[1024];
    int t = threadIdx.x;
    const int C = (NN + 1023) / 1024;
    int beg = t * C;
    int end = min(beg + C, NN);
    int s = 0;
    for (int v = beg; v < end; ++v) s += g_deg[v];
    partial[t] = s;
    __syncthreads();
    for (int off = 1; off < 1024; off <<= 1) {
        int val = (t >= off) ? partial[t - off] : 0;
        __syncthreads();
        partial[t] += val;
        __syncthreads();
    }
    int run = (t == 0) ? 0 : partial[t - 1];
    for (int v = beg; v < end; ++v) {
        int d = g_deg[v];
        g_rowptr[v] = run;
        g_invdeg[v] = 1.0f / (float)(d > 0 ? d : 1);
        run += d;
    }
    if (t == 1023) g_rowptr[NN] = run;
}

__global__ void fill_kernel(const int* __restrict__ src, const int* __restrict__ dst) {
    int i = blockIdx.x * blockDim.x + threadIdx.x;
    if (i * 4 + 3 < NE) {
        int4 s = ((const int4*)src)[i];
        int4 d = ((const int4*)dst)[i];
        int4 p = ((const int4*)g_epos)[i];
        g_esrc[g_rowptr[d.x] + p.x] = s.x;
        g_esrc[g_rowptr[d.y] + p.y] = s.y;
        g_esrc[g_rowptr[d.z] + p.z] = s.z;
        g_esrc[g_rowptr[d.w] + p.w] = s.w;
    } else {
        for (int e = i * 4; e < NE; ++e)
            g_esrc[g_rowptr[dst[e]] + g_epos[e]] = src[e];
    }
}

// ---------------- merged fp32 -> fp16 hi/lo split for all 5 weight mats ----------------
__global__ void convert_weights_kernel(const float* __restrict__ fcW,
                                       const float* __restrict__ W,
                                       const float* __restrict__ WL,
                                       __half* __restrict__ ohi,
                                       __half* __restrict__ olo) {
    int i = blockIdx.x * blockDim.x + threadIdx.x;
    if (i >= 18432) return;
    const float* srcp;
    if (i < 4096) srcp = fcW + 4 * (size_t)i;
    else if (i < 16384) srcp = W + 4 * (size_t)(i - 4096);
    else srcp = WL + 4 * (size_t)(i - 16384);
    float4 v = *(const float4*)srcp;
    __half h0, l0, h1, l1, h2, l2, h3, l3;
    split_fp16(v.x, h0, l0);
    split_fp16(v.y, h1, l1);
    split_fp16(v.z, h2, l2);
    split_fp16(v.w, h3, l3);
    uint2 uh, ul;
    uh.x = pack2h(h0, h1); uh.y = pack2h(h2, h3);
    ul.x = pack2h(l0, l1); ul.y = pack2h(l2, l3);
    ((uint2*)ohi)[i] = uh;
    ((uint2*)olo)[i] = ul;
}

// ---------------- aggregation: warp-per-node, all-fp16 gather + self ----------------
// x16[v] = fp16((1+eps[li]) * h16[v] + mean_{s in N(v)} h16[s])
__global__ void aggregate_kernel(const __half* __restrict__ h16,
                                 __half* __restrict__ x16,
                                 const float* __restrict__ eps, int li) {
    int warp = (blockIdx.x * blockDim.x + threadIdx.x) >> 5;
    if (warp >= NN) return;
    int lane = threadIdx.x & 31;
    int v = warp;
    int beg = g_rowptr[v], end = g_rowptr[v + 1];
    float4 acc = make_float4(0.f, 0.f, 0.f, 0.f);
    int e = beg;
    int col = lane * 4;
#define GATH(uv)                                                        \
    {                                                                   \
        __half2 p0 = *reinterpret_cast<const __half2*>(&(uv).x);        \
        __half2 p1 = *reinterpret_cast<const __half2*>(&(uv).y);        \
        float2 f0 = __half22float2(p0);                                 \
        float2 f1 = __half22float2(p1);                                 \
        acc.x += f0.x; acc.y += f0.y; acc.z += f1.x; acc.w += f1.y;     \
    }
    for (; e + 8 <= end; e += 8) {
        uint2 a0 = *(const uint2*)(h16 + (size_t)g_esrc[e + 0] * 128 + col);
        uint2 a1 = *(const uint2*)(h16 + (size_t)g_esrc[e + 1] * 128 + col);
        uint2 a2 = *(const uint2*)(h16 + (size_t)g_esrc[e + 2] * 128 + col);
        uint2 a3 = *(const uint2*)(h16 + (size_t)g_esrc[e + 3] * 128 + col);
        uint2 a4 = *(const uint2*)(h16 + (size_t)g_esrc[e + 4] * 128 + col);
        uint2 a5 = *(const uint2*)(h16 + (size_t)g_esrc[e + 5] * 128 + col);
        uint2 a6 = *(const uint2*)(h16 + (size_t)g_esrc[e + 6] * 128 + col);
        uint2 a7 = *(const uint2*)(h16 + (size_t)g_esrc[e + 7] * 128 + col);
        GATH(a0); GATH(a1); GATH(a2); GATH(a3);
        GATH(a4); GATH(a5); GATH(a6); GATH(a7);
    }
    for (; e + 4 <= end; e += 4) {
        uint2 a0 = *(const uint2*)(h16 + (size_t)g_esrc[e + 0] * 128 + col);
        uint2 a1 = *(const uint2*)(h16 + (size_t)g_esrc[e + 1] * 128 + col);
        uint2 a2 = *(const uint2*)(h16 + (size_t)g_esrc[e + 2] * 128 + col);
        uint2 a3 = *(const uint2*)(h16 + (size_t)g_esrc[e + 3] * 128 + col);
        GATH(a0); GATH(a1); GATH(a2); GATH(a3);
    }
    for (; e < end; ++e) {
        uint2 a = *(const uint2*)(h16 + (size_t)g_esrc[e] * 128 + col);
        GATH(a);
    }
#undef GATH
    float inv = g_invdeg[v];
    float sc = 1.0f + eps[li];
    uint2 sh = *(const uint2*)(h16 + (size_t)v * 128 + col);
    float2 s0 = __half22float2(*reinterpret_cast<const __half2*>(&sh.x));
    float2 s1 = __half22float2(*reinterpret_cast<const __half2*>(&sh.y));
    uint2 o;
    o.x = pack2h(__float2half_rn(sc * s0.x + acc.x * inv),
                 __float2half_rn(sc * s0.y + acc.y * inv));
    o.y = pack2h(__float2half_rn(sc * s1.x + acc.z * inv),
                 __float2half_rn(sc * s1.y + acc.w * inv));
    *(uint2*)&x16[(size_t)v * 128 + col] = o;
}

// ---------------- tensor-core GEMM: BM=64, 2-product fp16, 3 CTAs/SM ----------------
// out[M,N] = act(A @ (Whi+Wlo)^T + bias);  K chunked 2x64.
// F32OUT: write fp32 to out; else write fp16 to out16.
template <int N, bool RELU, bool ASPLIT, bool F32OUT>
__global__ void __launch_bounds__(256, 3) gemm_mma(
    const float* __restrict__ A32, const __half* __restrict__ A16,
    const __half* __restrict__ Bhi, const __half* __restrict__ Blo,
    const float* __restrict__ bias, float* __restrict__ out, __half* __restrict__ out16,
    int M) {
    constexpr int BM = 64;
    constexpr int LD = 72;            // 64 data cols + 8 pad (144B rows)
    constexpr int NWN = N / 32;       // 4 (N=128) or 2 (N=64)
    constexpr int NWM = 8 / NWN;      // 2 or 4
    constexpr int MW = BM / NWM;      // 32 or 16
    constexpr int MT = MW / 16;       // 2 or 1

    extern __shared__ __half sm[];
    __half* sA = sm;                   // BM x LD
    __half* sBhi = sA + BM * LD;       // N x LD
    __half* sBlo = sBhi + N * LD;
    __shared__ float s_bias[128];

    int tid = threadIdx.x;
    int lane = tid & 31;
    int wid = tid >> 5;
    int wm = wid / NWN;
    int wn = wid % NWN;
    int m0 = blockIdx.x * BM;
    if (tid < N) s_bias[tid] = bias[tid];

    float acc[MT][4][4];
#pragma unroll
    for (int mt = 0; mt < MT; ++mt)
#pragma unroll
        for (int nt = 0; nt < 4; ++nt)
#pragma unroll
            for (int q = 0; q < 4; ++q) acc[mt][nt][q] = 0.f;

    const int ar = lane & 15;
    const int ak = (lane >> 4) << 3;
    const int br = (lane & 7) + ((lane >> 4) << 3);
    const int bk = ((lane >> 3) & 1) << 3;

#pragma unroll
    for (int kc = 0; kc < 2; ++kc) {
        int kg = kc * 64;
        // stage B chunk: N rows x 64 cols, hi+lo
        for (int i = tid; i < N * 8; i += 256) {
            int row = i >> 3;
            int c8 = (i & 7) << 3;
            *(uint4*)&sBhi[row * LD + c8] = *(const uint4*)(Bhi + (size_t)row * 128 + kg + c8);
            *(uint4*)&sBlo[row * LD + c8] = *(const uint4*)(Blo + (size_t)row * 128 + kg + c8);
        }
        // stage A chunk: BM rows x 64 cols fp16
        if (ASPLIT) {
            for (int i = tid; i < BM * 8; i += 256) {
                int row = i >> 3;
                int c8 = (i & 7) << 3;
                int gm = m0 + row;
                float4 v0 = make_float4(0.f, 0.f, 0.f, 0.f);
                float4 v1 = make_float4(0.f, 0.f, 0.f, 0.f);
                if (gm < M) {
                    v0 = *(const float4*)(A32 + (size_t)gm * 128 + kg + c8);
                    v1 = *(const float4*)(A32 + (size_t)gm * 128 + kg + c8 + 4);
                }
                uint4 u;
                u.x = pack2h(__float2half_rn(v0.x), __float2half_rn(v0.y));
                u.y = pack2h(__float2half_rn(v0.z), __float2half_rn(v0.w));
                u.z = pack2h(__float2half_rn(v1.x), __float2half_rn(v1.y));
                u.w = pack2h(__float2half_rn(v1.z), __float2half_rn(v1.w));
                *(uint4*)&sA[row * LD + c8] = u;
            }
        } else {
            for (int i = tid; i < BM * 8; i += 256) {
                int row = i >> 3;
                int c8 = (i & 7) << 3;
                int gm = m0 + row;
                uint4 u = make_uint4(0, 0, 0, 0);
                if (gm < M) u = *(const uint4*)(A16 + (size_t)gm * 128 + kg + c8);
                *(uint4*)&sA[row * LD + c8] = u;
            }
        }
        __syncthreads();

#pragma unroll
        for (int ks = 0; ks < 4; ++ks) {
            int k0 = ks << 4;
            uint32_t a[MT][4];
#pragma unroll
            for (int mt = 0; mt < MT; ++mt) {
                int row = wm * MW + mt * 16 + ar;
                ldsm4(a[mt], smem_u32(&sA[row * LD + k0 + ak]));
            }
            uint32_t bh[4][2], bl[4][2];
#pragma unroll
            for (int p = 0; p < 2; ++p) {
                int nrow = wn * 32 + p * 16 + br;
                uint32_t r[4];
                ldsm4(r, smem_u32(&sBhi[nrow * LD + k0 + bk]));
                bh[2 * p][0] = r[0]; bh[2 * p][1] = r[1];
                bh[2 * p + 1][0] = r[2]; bh[2 * p + 1][1] = r[3];
                ldsm4(r, smem_u32(&sBlo[nrow * LD + k0 + bk]));
                bl[2 * p][0] = r[0]; bl[2 * p][1] = r[1];
                bl[2 * p + 1][0] = r[2]; bl[2 * p + 1][1] = r[3];
            }
#pragma unroll
            for (int mt = 0; mt < MT; ++mt)
#pragma unroll
                for (int nt = 0; nt < 4; ++nt) {
                    mma_fp16(acc[mt][nt], a[mt], bh[nt]);
                    mma_fp16(acc[mt][nt], a[mt], bl[nt]);
                }
        }
        __syncthreads();
    }

    int r = lane >> 2;
    int c2 = (lane & 3) << 1;
#pragma unroll
    for (int mt = 0; mt < MT; ++mt) {
        int gm = m0 + wm * MW + mt * 16 + r;
#pragma unroll
        for (int nt = 0; nt < 4; ++nt) {
            int col = wn * 32 + nt * 8 + c2;
            float b0 = s_bias[col], b1 = s_bias[col + 1];
            if (gm < M) {
                float2 v = make_float2(acc[mt][nt][0] + b0, acc[mt][nt][1] + b1);
                if (RELU) { v.x = fmaxf(v.x, 0.f); v.y = fmaxf(v.y, 0.f); }
                if (F32OUT)
                    *(float2*)(out + (size_t)gm * N + col) = v;
                else
                    *(uint32_t*)(out16 + (size_t)gm * N + col) =
                        pack2h(__float2half_rn(v.x), __float2half_rn(v.y));
            }
            if (gm + 8 < M) {
                float2 v = make_float2(acc[mt][nt][2] + b0, acc[mt][nt][3] + b1);
                if (RELU) { v.x = fmaxf(v.x, 0.f); v.y = fmaxf(v.y, 0.f); }
                if (F32OUT)
                    *(float2*)(out + (size_t)(gm + 8) * N + col) = v;
                else
                    *(uint32_t*)(out16 + (size_t)(gm + 8) * N + col) =
                        pack2h(__float2half_rn(v.x), __float2half_rn(v.y));
            }
        }
    }
}

// ---------------- launch ----------------
extern "C" void kernel_launch(void* const* d_in, const int* in_sizes, int n_in,
                              void* d_out, int out_size) {
    const float* inputs = (const float*)d_in[0];
    const float* fc_W   = (const float*)d_in[1];
    const float* fc_b   = (const float*)d_in[2];
    const float* W      = (const float*)d_in[3];
    const float* b      = (const float*)d_in[4];
    const float* W_last = (const float*)d_in[5];
    const float* b_last = (const float*)d_in[6];
    const float* eps    = (const float*)d_in[7];
    const int*   src    = (const int*)d_in[8];
    const int*   dst    = (const int*)d_in[9];
    float* out = (float*)d_out;

    __half *h16, *x16, *whi, *wlo;
    cudaGetSymbolAddress((void**)&h16, g_h16);
    cudaGetSymbolAddress((void**)&x16, g_x16);
    cudaGetSymbolAddress((void**)&whi, g_whi);
    cudaGetSymbolAddress((void**)&wlo, g_wlo);

    const int SMEM128 = (64 * 72 + 2 * 128 * 72) * 2;  // 46080 B
    const int SMEM64  = (64 * 72 + 2 * 64 * 72) * 2;   // 27648 B
    cudaFuncSetAttribute(gemm_mma<128, true, true, false>,  cudaFuncAttributeMaxDynamicSharedMemorySize, SMEM128);
    cudaFuncSetAttribute(gemm_mma<128, true, false, false>, cudaFuncAttributeMaxDynamicSharedMemorySize, SMEM128);
    cudaFuncSetAttribute(gemm_mma<64, false, false, true>,  cudaFuncAttributeMaxDynamicSharedMemorySize, SMEM64);

    const int gemm_grid = (NN + 63) / 64;  // 782
    const int agg_grid  = (NN + 7) / 8;

    // Order keeps our launch #3 (= ncu capture slot) on the SLP GEMM.
    convert_weights_kernel<<<(18432 + 255) / 256, 256>>>(fc_W, W, W_last, whi, wlo);  // 0
    zero_deg_kernel<<<(NN + 255) / 256, 256>>>();                                     // 1
    hist_kernel<<<(NE / 4 + 255) / 256, 256>>>(dst);                                  // 2
    gemm_mma<128, true, true, false><<<gemm_grid, 256, SMEM128>>>(                    // 3 (profiled)
        inputs, nullptr, whi, wlo, fc_b, nullptr, h16, NN);
    scan_kernel<<<1, 1024>>>();                                                       // 4
    fill_kernel<<<(NE / 4 + 255) / 256, 256>>>(src, dst);                             // 5

    // 3 hidden GIN layers (all-fp16 state)
    for (int i = 0; i < 3; ++i) {
        aggregate_kernel<<<agg_grid, 256>>>(h16, x16, eps, i);
        gemm_mma<128, true, false, false><<<gemm_grid, 256, SMEM128>>>(
            nullptr, x16, whi + (size_t)(1 + i) * 16384, wlo + (size_t)(1 + i) * 16384,
            b + (size_t)i * 128, nullptr, h16, NN);
    }

    // last GIN layer (no relu), fp32 straight into d_out
    aggregate_kernel<<<agg_grid, 256>>>(h16, x16, eps, 3);
    gemm_mma<64, false, false, true><<<gemm_grid, 256, SMEM64>>>(
        nullptr, x16, whi + (size_t)4 * 16384, wlo + (size_t)4 * 16384, b_last, out,
        nullptr, NN);

    (void)in_sizes; (void)n_in; (void)out_size;
}

// round 12
// speedup vs baseline: 1.3709x; 1.0350x over previous
#include <cuda_runtime.h>
#include <cuda_fp16.h>
#include <cstdint>

#define NN 50000
#define NE 800000

// ---------------- device scratch (no allocs allowed) ----------------
__device__ __align__(16) __half g_h16[NN * 128];
__device__ __align__(16) __half g_x16[NN * 128];
__device__ __align__(16) __half g_whi[5 * 128 * 128];
__device__ __align__(16) __half g_wlo[5 * 128 * 128];
__device__ int   g_deg[NN];
__device__ float g_invdeg[NN];
__device__ int   g_rowptr[NN + 1];
__device__ int   g_epos[NE];
__device__ int   g_esrc[NE];

// ---------------- helpers ----------------
__device__ __forceinline__ uint32_t smem_u32(const void* p) {
    uint32_t a;
    asm("{ .reg .u64 t; cvta.to.shared.u64 t, %1; cvt.u32.u64 %0, t; }" : "=r"(a) : "l"(p));
    return a;
}

__device__ __forceinline__ void ldsm4(uint32_t* r, uint32_t addr) {
    asm volatile("ldmatrix.sync.aligned.m8n8.x4.shared.b16 {%0,%1,%2,%3}, [%4];"
                 : "=r"(r[0]), "=r"(r[1]), "=r"(r[2]), "=r"(r[3]) : "r"(addr));
}

__device__ __forceinline__ void mma_fp16(float* c, const uint32_t* a, const uint32_t* b) {
    asm volatile(
        "mma.sync.aligned.m16n8k16.row.col.f32.f16.f16.f32 "
        "{%0,%1,%2,%3}, {%4,%5,%6,%7}, {%8,%9}, {%0,%1,%2,%3};"
        : "+f"(c[0]), "+f"(c[1]), "+f"(c[2]), "+f"(c[3])
        : "r"(a[0]), "r"(a[1]), "r"(a[2]), "r"(a[3]), "r"(b[0]), "r"(b[1]));
}

__device__ __forceinline__ void split_fp16(float v, __half& hi, __half& lo) {
    hi = __float2half_rn(v);
    lo = __float2half_rn(v - __half2float(hi));
}
__device__ __forceinline__ uint32_t pack2h(__half a, __half b) {
    __half2 t = __halves2half2(a, b);
    return *reinterpret_cast<uint32_t*>(&t);
}

// ---------------- CSR build ----------------
__global__ void zero_deg_kernel() {
    int v = blockIdx.x * blockDim.x + threadIdx.x;
    if (v < NN) g_deg[v] = 0;
}

__global__ void hist_kernel(const int* __restrict__ dst) {
    int i = blockIdx.x * blockDim.x + threadIdx.x;
    if (i * 4 + 3 < NE) {
        int4 d = ((const int4*)dst)[i];
        int4 p;
        p.x = atomicAdd(&g_deg[d.x], 1);
        p.y = atomicAdd(&g_deg[d.y], 1);
        p.z = atomicAdd(&g_deg[d.z], 1);
        p.w = atomicAdd(&g_deg[d.w], 1);
        ((int4*)g_epos)[i] = p;
    } else {
        for (int e = i * 4; e < NE; ++e) g_epos[e] = atomicAdd(&g_deg[dst[e]], 1);
    }
}

__global__ void scan_kernel() {
    __shared__ int partial[1024];
    int t = threadIdx.x;
    const int C = (NN + 1023) / 1024;
    int beg = t * C;
    int end = min(beg + C, NN);
    int s = 0;
    for (int v = beg; v < end; ++v) s += g_deg[v];
    partial[t] = s;
    __syncthreads();
    for (int off = 1; off < 1024; off <<= 1) {
        int val = (t >= off) ? partial[t - off] : 0;
        __syncthreads();
        partial[t] += val;
        __syncthreads();
    }
    int run = (t == 0) ? 0 : partial[t - 1];
    for (int v = beg; v < end; ++v) {
        int d = g_deg[v];
        g_rowptr[v] = run;
        g_invdeg[v] = 1.0f / (float)(d > 0 ? d : 1);
        run += d;
    }
    if (t == 1023) g_rowptr[NN] = run;
}

__global__ void fill_kernel(const int* __restrict__ src, const int* __restrict__ dst) {
    int i = blockIdx.x * blockDim.x + threadIdx.x;
    if (i * 4 + 3 < NE) {
        int4 s = ((const int4*)src)[i];
        int4 d = ((const int4*)dst)[i];
        int4 p = ((const int4*)g_epos)[i];
        g_esrc[g_rowptr[d.x] + p.x] = s.x;
        g_esrc[g_rowptr[d.y] + p.y] = s.y;
        g_esrc[g_rowptr[d.z] + p.z] = s.z;
        g_esrc[g_rowptr[d.w] + p.w] = s.w;
    } else {
        for (int e = i * 4; e < NE; ++e)
            g_esrc[g_rowptr[dst[e]] + g_epos[e]] = src[e];
    }
}

// ---------------- merged fp32 -> fp16 hi/lo split for all 5 weight mats ----------------
__global__ void convert_weights_kernel(const float* __restrict__ fcW,
                                       const float* __restrict__ W,
                                       const float* __restrict__ WL,
                                       __half* __restrict__ ohi,
                                       __half* __restrict__ olo) {
    int i = blockIdx.x * blockDim.x + threadIdx.x;
    if (i >= 18432) return;
    const float* srcp;
    if (i < 4096) srcp = fcW + 4 * (size_t)i;
    else if (i < 16384) srcp = W + 4 * (size_t)(i - 4096);
    else srcp = WL + 4 * (size_t)(i - 16384);
    float4 v = *(const float4*)srcp;
    __half h0, l0, h1, l1, h2, l2, h3, l3;
    split_fp16(v.x, h0, l0);
    split_fp16(v.y, h1, l1);
    split_fp16(v.z, h2, l2);
    split_fp16(v.w, h3, l3);
    uint2 uh, ul;
    uh.x = pack2h(h0, h1); uh.y = pack2h(h2, h3);
    ul.x = pack2h(l0, l1); ul.y = pack2h(l2, l3);
    ((uint2*)ohi)[i] = uh;
    ((uint2*)olo)[i] = ul;
}

// ---------------- aggregation: warp-per-node, all-fp16 gather + self ----------------
__global__ void aggregate_kernel(const __half* __restrict__ h16,
                                 __half* __restrict__ x16,
                                 const float* __restrict__ eps, int li) {
    int warp = (blockIdx.x * blockDim.x + threadIdx.x) >> 5;
    if (warp >= NN) return;
    int lane = threadIdx.x & 31;
    int v = warp;
    int beg = g_rowptr[v], end = g_rowptr[v + 1];
    float4 acc = make_float4(0.f, 0.f, 0.f, 0.f);
    int e = beg;
    int col = lane * 4;
#define GATH(uv)                                                        \
    {                                                                   \
        __half2 p0 = *reinterpret_cast<const __half2*>(&(uv).x);        \
        __half2 p1 = *reinterpret_cast<const __half2*>(&(uv).y);        \
        float2 f0 = __half22float2(p0);                                 \
        float2 f1 = __half22float2(p1);                                 \
        acc.x += f0.x; acc.y += f0.y; acc.z += f1.x; acc.w += f1.y;     \
    }
    for (; e + 8 <= end; e += 8) {
        uint2 a0 = *(const uint2*)(h16 + (size_t)g_esrc[e + 0] * 128 + col);
        uint2 a1 = *(const uint2*)(h16 + (size_t)g_esrc[e + 1] * 128 + col);
        uint2 a2 = *(const uint2*)(h16 + (size_t)g_esrc[e + 2] * 128 + col);
        uint2 a3 = *(const uint2*)(h16 + (size_t)g_esrc[e + 3] * 128 + col);
        uint2 a4 = *(const uint2*)(h16 + (size_t)g_esrc[e + 4] * 128 + col);
        uint2 a5 = *(const uint2*)(h16 + (size_t)g_esrc[e + 5] * 128 + col);
        uint2 a6 = *(const uint2*)(h16 + (size_t)g_esrc[e + 6] * 128 + col);
        uint2 a7 = *(const uint2*)(h16 + (size_t)g_esrc[e + 7] * 128 + col);
        GATH(a0); GATH(a1); GATH(a2); GATH(a3);
        GATH(a4); GATH(a5); GATH(a6); GATH(a7);
    }
    for (; e + 4 <= end; e += 4) {
        uint2 a0 = *(const uint2*)(h16 + (size_t)g_esrc[e + 0] * 128 + col);
        uint2 a1 = *(const uint2*)(h16 + (size_t)g_esrc[e + 1] * 128 + col);
        uint2 a2 = *(const uint2*)(h16 + (size_t)g_esrc[e + 2] * 128 + col);
        uint2 a3 = *(const uint2*)(h16 + (size_t)g_esrc[e + 3] * 128 + col);
        GATH(a0); GATH(a1); GATH(a2); GATH(a3);
    }
    for (; e < end; ++e) {
        uint2 a = *(const uint2*)(h16 + (size_t)g_esrc[e] * 128 + col);
        GATH(a);
    }
#undef GATH
    float inv = g_invdeg[v];
    float sc = 1.0f + eps[li];
    uint2 sh = *(const uint2*)(h16 + (size_t)v * 128 + col);
    float2 s0 = __half22float2(*reinterpret_cast<const __half2*>(&sh.x));
    float2 s1 = __half22float2(*reinterpret_cast<const __half2*>(&sh.y));
    uint2 o;
    o.x = pack2h(__float2half_rn(sc * s0.x + acc.x * inv),
                 __float2half_rn(sc * s0.y + acc.y * inv));
    o.y = pack2h(__float2half_rn(sc * s1.x + acc.z * inv),
                 __float2half_rn(sc * s1.y + acc.w * inv));
    *(uint2*)&x16[(size_t)v * 128 + col] = o;
}

// ---------------- tensor-core GEMM: BM=64, 2-product fp16, 3 CTAs/SM ----------------
template <int N, bool RELU, bool ASPLIT, bool F32OUT>
__global__ void __launch_bounds__(256, 3) gemm_mma(
    const float* __restrict__ A32, const __half* __restrict__ A16,
    const __half* __restrict__ Bhi, const __half* __restrict__ Blo,
    const float* __restrict__ bias, float* __restrict__ out, __half* __restrict__ out16,
    int M) {
    constexpr int BM = 64;
    constexpr int LD = 72;
    constexpr int NWN = N / 32;
    constexpr int NWM = 8 / NWN;
    constexpr int MW = BM / NWM;
    constexpr int MT = MW / 16;

    extern __shared__ __half sm[];
    __half* sA = sm;
    __half* sBhi = sA + BM * LD;
    __half* sBlo = sBhi + N * LD;
    __shared__ float s_bias[128];

    int tid = threadIdx.x;
    int lane = tid & 31;
    int wid = tid >> 5;
    int wm = wid / NWN;
    int wn = wid % NWN;
    int m0 = blockIdx.x * BM;
    if (tid < N) s_bias[tid] = bias[tid];

    float acc[MT][4][4];
#pragma unroll
    for (int mt = 0; mt < MT; ++mt)
#pragma unroll
        for (int nt = 0; nt < 4; ++nt)
#pragma unroll
            for (int q = 0; q < 4; ++q) acc[mt][nt][q] = 0.f;

    const int ar = lane & 15;
    const int ak = (lane >> 4) << 3;
    const int br = (lane & 7) + ((lane >> 4) << 3);
    const int bk = ((lane >> 3) & 1) << 3;

#pragma unroll
    for (int kc = 0; kc < 2; ++kc) {
        int kg = kc * 64;
        for (int i = tid; i < N * 8; i += 256) {
            int row = i >> 3;
            int c8 = (i & 7) << 3;
            *(uint4*)&sBhi[row * LD + c8] = *(const uint4*)(Bhi + (size_t)row * 128 + kg + c8);
            *(uint4*)&sBlo[row * LD + c8] = *(const uint4*)(Blo + (size_t)row * 128 + kg + c8);
        }
        if (ASPLIT) {
            for (int i = tid; i < BM * 8; i += 256) {
                int row = i >> 3;
                int c8 = (i & 7) << 3;
                int gm = m0 + row;
                float4 v0 = make_float4(0.f, 0.f, 0.f, 0.f);
                float4 v1 = make_float4(0.f, 0.f, 0.f, 0.f);
                if (gm < M) {
                    v0 = *(const float4*)(A32 + (size_t)gm * 128 + kg + c8);
                    v1 = *(const float4*)(A32 + (size_t)gm * 128 + kg + c8 + 4);
                }
                uint4 u;
                u.x = pack2h(__float2half_rn(v0.x), __float2half_rn(v0.y));
                u.y = pack2h(__float2half_rn(v0.z), __float2half_rn(v0.w));
                u.z = pack2h(__float2half_rn(v1.x), __float2half_rn(v1.y));
                u.w = pack2h(__float2half_rn(v1.z), __float2half_rn(v1.w));
                *(uint4*)&sA[row * LD + c8] = u;
            }
        } else {
            for (int i = tid; i < BM * 8; i += 256) {
                int row = i >> 3;
                int c8 = (i & 7) << 3;
                int gm = m0 + row;
                uint4 u = make_uint4(0, 0, 0, 0);
                if (gm < M) u = *(const uint4*)(A16 + (size_t)gm * 128 + kg + c8);
                *(uint4*)&sA[row * LD + c8] = u;
            }
        }
        __syncthreads();

#pragma unroll
        for (int ks = 0; ks < 4; ++ks) {
            int k0 = ks << 4;
            uint32_t a[MT][4];
#pragma unroll
            for (int mt = 0; mt < MT; ++mt) {
                int row = wm * MW + mt * 16 + ar;
                ldsm4(a[mt], smem_u32(&sA[row * LD + k0 + ak]));
            }
            uint32_t bh[4][2], bl[4][2];
#pragma unroll
            for (int p = 0; p < 2; ++p) {
                int nrow = wn * 32 + p * 16 + br;
                uint32_t r[4];
                ldsm4(r, smem_u32(&sBhi[nrow * LD + k0 + bk]));
                bh[2 * p][0] = r[0]; bh[2 * p][1] = r[1];
                bh[2 * p + 1][0] = r[2]; bh[2 * p + 1][1] = r[3];
                ldsm4(r, smem_u32(&sBlo[nrow * LD + k0 + bk]));
                bl[2 * p][0] = r[0]; bl[2 * p][1] = r[1];
                bl[2 * p + 1][0] = r[2]; bl[2 * p + 1][1] = r[3];
            }
#pragma unroll
            for (int mt = 0; mt < MT; ++mt)
#pragma unroll
                for (int nt = 0; nt < 4; ++nt) {
                    mma_fp16(acc[mt][nt], a[mt], bh[nt]);
                    mma_fp16(acc[mt][nt], a[mt], bl[nt]);
                }
        }
        __syncthreads();
    }

    int r = lane >> 2;
    int c2 = (lane & 3) << 1;
#pragma unroll
    for (int mt = 0; mt < MT; ++mt) {
        int gm = m0 + wm * MW + mt * 16 + r;
#pragma unroll
        for (int nt = 0; nt < 4; ++nt) {
            int col = wn * 32 + nt * 8 + c2;
            float b0 = s_bias[col], b1 = s_bias[col + 1];
            if (gm < M) {
                float2 v = make_float2(acc[mt][nt][0] + b0, acc[mt][nt][1] + b1);
                if (RELU) { v.x = fmaxf(v.x, 0.f); v.y = fmaxf(v.y, 0.f); }
                if (F32OUT)
                    *(float2*)(out + (size_t)gm * N + col) = v;
                else
                    *(uint32_t*)(out16 + (size_t)gm * N + col) =
                        pack2h(__float2half_rn(v.x), __float2half_rn(v.y));
            }
            if (gm + 8 < M) {
                float2 v = make_float2(acc[mt][nt][2] + b0, acc[mt][nt][3] + b1);
                if (RELU) { v.x = fmaxf(v.x, 0.f); v.y = fmaxf(v.y, 0.f); }
                if (F32OUT)
                    *(float2*)(out + (size_t)(gm + 8) * N + col) = v;
                else
                    *(uint32_t*)(out16 + (size_t)(gm + 8) * N + col) =
                        pack2h(__float2half_rn(v.x), __float2half_rn(v.y));
            }
        }
    }
}

// ---------------- launch ----------------
extern "C" void kernel_launch(void* const* d_in, const int* in_sizes, int n_in,
                              void* d_out, int out_size) {
    const float* inputs = (const float*)d_in[0];
    const float* fc_W   = (const float*)d_in[1];
    const float* fc_b   = (const float*)d_in[2];
    const float* W      = (const float*)d_in[3];
    const float* b      = (const float*)d_in[4];
    const float* W_last = (const float*)d_in[5];
    const float* b_last = (const float*)d_in[6];
    const float* eps    = (const float*)d_in[7];
    const int*   src    = (const int*)d_in[8];
    const int*   dst    = (const int*)d_in[9];
    float* out = (float*)d_out;

    __half *h16, *x16, *whi, *wlo;
    cudaGetSymbolAddress((void**)&h16, g_h16);
    cudaGetSymbolAddress((void**)&x16, g_x16);
    cudaGetSymbolAddress((void**)&whi, g_whi);
    cudaGetSymbolAddress((void**)&wlo, g_wlo);

    const int SMEM128 = (64 * 72 + 2 * 128 * 72) * 2;  // 46080 B
    const int SMEM64  = (64 * 72 + 2 * 64 * 72) * 2;   // 27648 B
    cudaFuncSetAttribute(gemm_mma<128, true, true, false>,  cudaFuncAttributeMaxDynamicSharedMemorySize, SMEM128);
    cudaFuncSetAttribute(gemm_mma<128, true, false, false>, cudaFuncAttributeMaxDynamicSharedMemorySize, SMEM128);
    cudaFuncSetAttribute(gemm_mma<64, false, false, true>,  cudaFuncAttributeMaxDynamicSharedMemorySize, SMEM64);

    // One-time side stream + fork/join events (created on the first, non-capture,
    // correctness call; only launches/event-ops happen during capture).
    static cudaStream_t s_side = nullptr;
    static cudaEvent_t s_fork = nullptr, s_join = nullptr;
    if (s_side == nullptr) {
        cudaStreamCreateWithFlags(&s_side, cudaStreamNonBlocking);
        cudaEventCreateWithFlags(&s_fork, cudaEventDisableTiming);
        cudaEventCreateWithFlags(&s_join, cudaEventDisableTiming);
    }

    const int gemm_grid = (NN + 63) / 64;  // 782
    const int agg_grid  = (NN + 7) / 8;

    // ---- forked phase: CSR build (side stream) || convert + SLP GEMM (main) ----
    convert_weights_kernel<<<(18432 + 255) / 256, 256>>>(fc_W, W, W_last, whi, wlo);  // main #0
    cudaEventRecord(s_fork, 0);
    cudaStreamWaitEvent(s_side, s_fork, 0);

    zero_deg_kernel<<<(NN + 255) / 256, 256, 0, s_side>>>();                          // side #1
    hist_kernel<<<(NE / 4 + 255) / 256, 256, 0, s_side>>>(dst);                       // side #2
    gemm_mma<128, true, true, false><<<gemm_grid, 256, SMEM128>>>(                    // main #3 (profiled slot)
        inputs, nullptr, whi, wlo, fc_b, nullptr, h16, NN);
    scan_kernel<<<1, 1024, 0, s_side>>>();                                            // side #4
    fill_kernel<<<(NE / 4 + 255) / 256, 256, 0, s_side>>>(src, dst);                  // side #5

    cudaEventRecord(s_join, s_side);
    cudaStreamWaitEvent(0, s_join, 0);

    // ---- serial phase: 3 hidden GIN layers (all-fp16 state) ----
    for (int i = 0; i < 3; ++i) {
        aggregate_kernel<<<agg_grid, 256>>>(h16, x16, eps, i);
        gemm_mma<128, true, false, false><<<gemm_grid, 256, SMEM128>>>(
            nullptr, x16, whi + (size_t)(1 + i) * 16384, wlo + (size_t)(1 + i) * 16384,
            b + (size_t)i * 128, nullptr, h16, NN);
    }

    // last GIN layer (no relu), fp32 straight into d_out
    aggregate_kernel<<<agg_grid, 256>>>(h16, x16, eps, 3);
    gemm_mma<64, false, false, true><<<gemm_grid, 256, SMEM64>>>(
        nullptr, x16, whi + (size_t)4 * 16384, wlo + (size_t)4 * 16384, b_last, out,
        nullptr, NN);

    (void)in_sizes; (void)n_in; (void)out_size;
}